// round 11
// baseline (speedup 1.0000x reference)
#include <cuda_runtime.h>
#include <cuda_bf16.h>
#include <cstdint>

#define Nn 100000
#define Ee 1600000
#define FIN 128
#define K1 129
#define HD 128
#define NCARDS 110
#define TILE_M 128
#define NTILES ((Nn + TILE_M - 1) / TILE_M)   // 782
#define TSPLIT 391
#define NSPLIT (TSPLIT * TILE_M)              // 50048

typedef unsigned int u32;

// ---------------- device scratch ----------------
__device__ __nv_bfloat16 g_b0h[(size_t)Nn * HD], g_b0l[(size_t)Nn * HD];
__device__ __nv_bfloat16 g_b1h[(size_t)Nn * HD], g_b1l[(size_t)Nn * HD];
__device__ __nv_bfloat16 g_b2h[(size_t)Nn * HD], g_b2l[(size_t)Nn * HD];
__device__ __nv_bfloat16 g_bsh[(size_t)Nn * HD], g_bsl[(size_t)Nn * HD];
__device__ float g_cardf[Nn];
__device__ float g_meanC[Nn];
__device__ __nv_bfloat16 g_Whi[5][HD * HD];
__device__ __nv_bfloat16 g_Wlo[5][HD * HD];
__device__ int g_degc[Nn];
__device__ int g_cnt[Nn];
__device__ int g_offs[Nn];
__device__ int g_csrc[Ee];
__device__ int g_tot;
__device__ int g_is64;

// ---------------- helpers ----------------
__device__ __forceinline__ unsigned load_ei(const int* p, size_t i, int is64) {
    if (is64) return (unsigned)((const long long*)p)[i];
    return (unsigned)p[i];
}
__device__ __forceinline__ uint32_t smem_u32(const void* p) {
    uint32_t a;
    asm("{ .reg .u64 t; cvta.to.shared.u64 t, %1; cvt.u32.u64 %0, t; }" : "=r"(a) : "l"(p));
    return a;
}
__device__ __forceinline__ u32 cvt2(float a, float b) {
    __nv_bfloat162 t = __floats2bfloat162_rn(a, b);
    return *(u32*)&t;
}
__device__ __forceinline__ void split2(float f0, float f1, u32& hw, u32& lw) {
    __nv_bfloat16 h0 = __float2bfloat16_rn(f0);
    __nv_bfloat16 h1 = __float2bfloat16_rn(f1);
    hw = ((u32)*(unsigned short*)&h1 << 16) | *(unsigned short*)&h0;
    lw = cvt2(f0 - __bfloat162float(h0), f1 - __bfloat162float(h1));
}
__device__ __forceinline__ void acc4(float4& a, uint2 h, uint2 l) {
    float2 h0 = __bfloat1622float2(*(__nv_bfloat162*)&h.x);
    float2 h1 = __bfloat1622float2(*(__nv_bfloat162*)&h.y);
    float2 l0 = __bfloat1622float2(*(__nv_bfloat162*)&l.x);
    float2 l1 = __bfloat1622float2(*(__nv_bfloat162*)&l.y);
    a.x += h0.x + l0.x; a.y += h0.y + l0.y;
    a.z += h1.x + l1.x; a.w += h1.y + l1.y;
}

#define LDM4(r, addr) \
    asm volatile("ldmatrix.sync.aligned.m8n8.x4.shared.b16 {%0,%1,%2,%3}, [%4];" \
                 : "=r"((r)[0]), "=r"((r)[1]), "=r"((r)[2]), "=r"((r)[3]) : "r"(addr))

#define MMA(c, a, bb0, bb1) \
    asm volatile("mma.sync.aligned.m16n8k16.row.col.f32.bf16.bf16.f32 " \
                 "{%0,%1,%2,%3},{%4,%5,%6,%7},{%8,%9},{%0,%1,%2,%3};" \
                 : "+f"((c)[0]), "+f"((c)[1]), "+f"((c)[2]), "+f"((c)[3]) \
                 : "r"((a)[0]), "r"((a)[1]), "r"((a)[2]), "r"((a)[3]), "r"(bb0), "r"(bb1))

#define CPA(dst, src) \
    asm volatile("cp.async.cg.shared.global [%0], [%1], 16;" :: "r"(dst), "l"(src))
#define CPA_COMMIT() asm volatile("cp.async.commit_group;" ::: "memory")
#define CPA_WAIT()   asm volatile("cp.async.wait_group 0;" ::: "memory")

#define RS 272
#define S_AHI 0
#define S_ALO 34816
#define S_WHI 69632
#define S_WLO 87040
#define S_AUX 104448
#define SMEM_DYN (104448 + 3 * 64 * 4)

// ---------------- gather core ----------------
__device__ __forceinline__ void gather_range(
    const __nv_bfloat16* __restrict__ sh_, const __nv_bfloat16* __restrict__ sl_,
    int layer0, int gw, int nw, int lane, int nFrom, int nTo)
{
    for (int n = nFrom + gw; n < nTo; n += nw) {
        int st = g_offs[n];
        int dg = g_degc[n];
        if (st < 0) st = 0;
        if (st + dg > Ee) dg = Ee - st;
        float4 acc = make_float4(0.f, 0.f, 0.f, 0.f);
        float accC = 0.f;
        int i = 0;
        for (; i + 4 <= dg; i += 4) {
            int s0 = g_csrc[st + i];
            int s1 = g_csrc[st + i + 1];
            int s2 = g_csrc[st + i + 2];
            int s3 = g_csrc[st + i + 3];
            uint2 h0 = *(const uint2*)(sh_ + (size_t)s0 * HD + lane * 4);
            uint2 l0 = *(const uint2*)(sl_ + (size_t)s0 * HD + lane * 4);
            uint2 h1 = *(const uint2*)(sh_ + (size_t)s1 * HD + lane * 4);
            uint2 l1 = *(const uint2*)(sl_ + (size_t)s1 * HD + lane * 4);
            uint2 h2 = *(const uint2*)(sh_ + (size_t)s2 * HD + lane * 4);
            uint2 l2 = *(const uint2*)(sl_ + (size_t)s2 * HD + lane * 4);
            uint2 h3 = *(const uint2*)(sh_ + (size_t)s3 * HD + lane * 4);
            uint2 l3 = *(const uint2*)(sl_ + (size_t)s3 * HD + lane * 4);
            acc4(acc, h0, l0); acc4(acc, h1, l1);
            acc4(acc, h2, l2); acc4(acc, h3, l3);
            if (layer0 && lane == 0)
                accC += g_cardf[s0] + g_cardf[s1] + g_cardf[s2] + g_cardf[s3];
        }
        for (; i < dg; ++i) {
            int s = g_csrc[st + i];
            uint2 h = *(const uint2*)(sh_ + (size_t)s * HD + lane * 4);
            uint2 l = *(const uint2*)(sl_ + (size_t)s * HD + lane * 4);
            acc4(acc, h, l);
            if (layer0 && lane == 0) accC += g_cardf[s];
        }
        float di = (dg > 0) ? 1.f / (float)dg : 0.f;
        acc.x *= di; acc.y *= di; acc.z *= di; acc.w *= di;
        uint2 hv, lv;
        split2(acc.x, acc.y, hv.x, lv.x);
        split2(acc.z, acc.w, hv.y, lv.y);
        *(uint2*)(g_bsh + (size_t)n * HD + lane * 4) = hv;
        *(uint2*)(g_bsl + (size_t)n * HD + lane * 4) = lv;
        if (layer0 && lane == 0) g_meanC[n] = accC * di;
    }
}

// ---------------- mma tile core (128m x 64n) ----------------
__device__ __forceinline__ void mma_tile(
    char* smem, uint32_t sb, int n0, int c_base, int tid,
    const __nv_bfloat16* __restrict__ A0h, const __nv_bfloat16* __restrict__ A0l,
    const __nv_bfloat16* __restrict__ A1h, const __nv_bfloat16* __restrict__ A1l,
    int w0, int w1,
    const float* __restrict__ b0, const float* __restrict__ b1,
    const float* __restrict__ r1wl, const float* __restrict__ r1wr,
    int numOps, int do_relu,
    float* __restrict__ fout, int ostride, int ocols,
    __nv_bfloat16* __restrict__ bh_out, __nv_bfloat16* __restrict__ bl_out)
{
    float* auxb = (float*)(smem + S_AUX);
    float* auxl = auxb + 64;
    float* auxr = auxl + 64;
    int wid = tid >> 5;
    int lane = tid & 31;
    int wr0 = wid * 16;

    if (tid < 64) {
        int cg = c_base + tid;
        float bs = (cg < ocols) ? b0[cg] : 0.f;
        if (b1 && cg < ocols) bs += b1[cg];
        auxb[tid] = bs;
        auxl[tid] = r1wl ? r1wl[(size_t)cg * K1] : 0.f;
        auxr[tid] = r1wr ? r1wr[(size_t)cg * K1] : 0.f;
    }

    float acc[8][4];
#pragma unroll
    for (int i = 0; i < 8; i++)
#pragma unroll
        for (int j = 0; j < 4; j++) acc[i][j] = 0.f;

    int q = lane >> 3, r8 = lane & 7;
    uint32_t qrow = (uint32_t)((q & 1) * 8 + r8);
    uint32_t qkb = (uint32_t)((q >> 1) * 16);
    uint32_t a_off = (wr0 + qrow) * RS + qkb;

    for (int op = 0; op < numOps; ++op) {
        if (op) __syncthreads();
        const __nv_bfloat16* Ah = op ? A1h : A0h;
        const __nv_bfloat16* Al = op ? A1l : A0l;
        const __nv_bfloat16* Wh = g_Whi[op ? w1 : w0];
        const __nv_bfloat16* Wl = g_Wlo[op ? w1 : w0];
        {
            int r = tid >> 1, half = tid & 1;
            int m = n0 + r;
            uint32_t dh = sb + S_AHI + r * RS + half * 128;
            uint32_t dl = sb + S_ALO + r * RS + half * 128;
            if (m < Nn) {
                const char* srch = (const char*)(Ah + (size_t)m * HD + half * 64);
                const char* srcl = (const char*)(Al + (size_t)m * HD + half * 64);
#pragma unroll
                for (int qq = 0; qq < 8; ++qq) {
                    CPA(dh + qq * 16, srch + qq * 16);
                    CPA(dl + qq * 16, srcl + qq * 16);
                }
            } else {
                uint4 z = make_uint4(0, 0, 0, 0);
#pragma unroll
                for (int qq = 0; qq < 8; ++qq) {
                    *(uint4*)(smem + S_AHI + r * RS + half * 128 + qq * 16) = z;
                    *(uint4*)(smem + S_ALO + r * RS + half * 128 + qq * 16) = z;
                }
            }
        }
        {
            int r = tid >> 2, qtr = tid & 3;
            int nrow = c_base + r;
            const char* srch = (const char*)(Wh + (size_t)nrow * HD + qtr * 32);
            const char* srcl = (const char*)(Wl + (size_t)nrow * HD + qtr * 32);
            uint32_t dh = sb + S_WHI + r * RS + qtr * 64;
            uint32_t dl = sb + S_WLO + r * RS + qtr * 64;
#pragma unroll
            for (int qq = 0; qq < 4; ++qq) {
                CPA(dh + qq * 16, srch + qq * 16);
                CPA(dl + qq * 16, srcl + qq * 16);
            }
        }
        CPA_COMMIT();
        CPA_WAIT();
        __syncthreads();

#pragma unroll
        for (int ks = 0; ks < 8; ++ks) {
            uint32_t kb = ks * 32;
            u32 ah[4], al[4];
            LDM4(ah, sb + S_AHI + a_off + kb);
            LDM4(al, sb + S_ALO + a_off + kb);
#pragma unroll
            for (int p = 0; p < 4; ++p) {
                uint32_t boff = (p * 16 + qrow) * RS + qkb + kb;
                u32 bh[4], bl[4];
                LDM4(bh, sb + S_WHI + boff);
                LDM4(bl, sb + S_WLO + boff);
                MMA(acc[2 * p],     ah, bh[0], bh[2]);
                MMA(acc[2 * p],     ah, bl[0], bl[2]);
                MMA(acc[2 * p],     al, bh[0], bh[2]);
                MMA(acc[2 * p + 1], ah, bh[1], bh[3]);
                MMA(acc[2 * p + 1], ah, bl[1], bl[3]);
                MMA(acc[2 * p + 1], al, bh[1], bh[3]);
            }
        }
    }

    int l4 = lane >> 2, c2 = (lane & 3) * 2;
    int rA = n0 + wr0 + l4;
    int rB = rA + 8;
    float mcA = 0.f, scA = 0.f, mcB = 0.f, scB = 0.f;
    if (r1wl) {
        if (rA < Nn) { mcA = g_meanC[rA]; scA = g_cardf[rA]; }
        if (rB < Nn) { mcB = g_meanC[rB]; scB = g_cardf[rB]; }
    }
#pragma unroll
    for (int nt = 0; nt < 8; ++nt) {
        int c = nt * 8 + c2;
        int gc = c_base + c;
        float f0 = acc[nt][0] + auxb[c]     + mcA * auxl[c]     + scA * auxr[c];
        float f1 = acc[nt][1] + auxb[c + 1] + mcA * auxl[c + 1] + scA * auxr[c + 1];
        float f2 = acc[nt][2] + auxb[c]     + mcB * auxl[c]     + scB * auxr[c];
        float f3 = acc[nt][3] + auxb[c + 1] + mcB * auxl[c + 1] + scB * auxr[c + 1];
        if (do_relu) {
            f0 = fmaxf(f0, 0.f); f1 = fmaxf(f1, 0.f);
            f2 = fmaxf(f2, 0.f); f3 = fmaxf(f3, 0.f);
        }
        if (fout) {
            if (rA < Nn) {
                if (gc < ocols)     fout[(size_t)rA * ostride + gc]     = f0;
                if (gc + 1 < ocols) fout[(size_t)rA * ostride + gc + 1] = f1;
            }
            if (rB < Nn) {
                if (gc < ocols)     fout[(size_t)rB * ostride + gc]     = f2;
                if (gc + 1 < ocols) fout[(size_t)rB * ostride + gc + 1] = f3;
            }
        }
        if (bh_out) {
            u32 hw, lw;
            if (rA < Nn) {
                split2(f0, f1, hw, lw);
                *(u32*)(bh_out + (size_t)rA * HD + gc) = hw;
                *(u32*)(bl_out + (size_t)rA * HD + gc) = lw;
            }
            if (rB < Nn) {
                split2(f2, f3, hw, lw);
                *(u32*)(bh_out + (size_t)rB * HD + gc) = hw;
                *(u32*)(bl_out + (size_t)rB * HD + gc) = lw;
            }
        }
    }
}

// ---------------- setup kernels ----------------
__global__ void k_init(const int* __restrict__ ei32) {
    int i = blockIdx.x * blockDim.x + threadIdx.x;
    if (i < Nn) { g_degc[i] = 0; g_cnt[i] = 0; }
    if (i == 0) {
        g_tot = 0;
        int all_zero = 1;
        for (int w = 1; w < 64; w += 2)
            if (ei32[w] != 0) { all_zero = 0; break; }
        g_is64 = all_zero;
    }
}

#define NB_CONCAT 12500
#define NB_DEG 6250
#define NB_PREP 320

// merged: concat || deghist || prep_w
__global__ void k_setupC(const float* __restrict__ x, const int* __restrict__ cards,
                         const int* __restrict__ ei,
                         const float* __restrict__ Wl1, const float* __restrict__ Wr1,
                         const float* __restrict__ Wl2, const float* __restrict__ Wr2,
                         const float* __restrict__ Wo) {
    int bid = blockIdx.x;
    int tid = threadIdx.x;
    if (bid < NB_CONCAT) {
        int i = bid * 256 + tid;
        if (i >= Nn * 32) return;
        int n = i >> 5, c = (i & 31) * 4;
        float4 v = *(const float4*)(x + (size_t)n * FIN + c);
        uint2 hv, lv;
        split2(v.x, v.y, hv.x, lv.x);
        split2(v.z, v.w, hv.y, lv.y);
        *(uint2*)(g_b0h + (size_t)n * HD + c) = hv;
        *(uint2*)(g_b0l + (size_t)n * HD + c) = lv;
        if ((i & 31) == 0) g_cardf[n] = (float)cards[n];
    } else if (bid < NB_CONCAT + NB_DEG) {
        int e = (bid - NB_CONCAT) * 256 + tid;
        if (e < Ee) {
            unsigned d = load_ei(ei, (size_t)Ee + e, g_is64);
            if (d < Nn) atomicAdd(&g_degc[d], 1);
        }
    } else {
        int i = (bid - NB_CONCAT - NB_DEG) * 256 + tid;
        if (i >= 5 * HD * HD) return;
        int op = i / (HD * HD);
        int r = i % (HD * HD);
        int n = r / HD, k = r % HD;
        float v = 0.f;
        if (op == 0) v = Wl1[n * K1 + k];
        else if (op == 1) v = Wr1[n * K1 + k];
        else if (op == 2) v = Wl2[n * HD + k];
        else if (op == 3) v = Wr2[n * HD + k];
        else if (n < NCARDS) v = Wo[n * HD + k];
        __nv_bfloat16 h = __float2bfloat16_rn(v);
        g_Whi[op][r] = h;
        g_Wlo[op][r] = __float2bfloat16_rn(v - __bfloat162float(h));
    }
}

__global__ void k_scanA() {
    __shared__ int sh[1024];
    __shared__ int base;
    int t = threadIdx.x;
    int n = blockIdx.x * 1024 + t;
    int v = (n < Nn) ? g_degc[n] : 0;
    sh[t] = v;
    __syncthreads();
    for (int off = 1; off < 1024; off <<= 1) {
        int add = (t >= off) ? sh[t - off] : 0;
        __syncthreads();
        sh[t] += add;
        __syncthreads();
    }
    if (t == 1023) base = atomicAdd(&g_tot, sh[1023]);
    __syncthreads();
    if (n < Nn) g_offs[n] = base + sh[t] - v;
}

__global__ void k_place(const int* __restrict__ ei) {
    int e = blockIdx.x * blockDim.x + threadIdx.x;
    if (e < Ee) {
        int is64 = g_is64;
        unsigned s = load_ei(ei, (size_t)e, is64);
        unsigned d = load_ei(ei, (size_t)Ee + e, is64);
        if (s < Nn && d < Nn) {
            int pos = g_offs[d] + atomicAdd(&g_cnt[d], 1);
            if (pos >= 0 && pos < Ee) g_csrc[pos] = (int)s;
        }
    }
}

// ---------------- pure gather ----------------
__global__ void k_gather(const __nv_bfloat16* __restrict__ sh_,
                         const __nv_bfloat16* __restrict__ sl_,
                         int layer0, int nFrom, int nTo) {
    int gw = (blockIdx.x * blockDim.x + threadIdx.x) >> 5;
    int nw = (gridDim.x * blockDim.x) >> 5;
    gather_range(sh_, sl_, layer0, gw, nw, threadIdx.x & 31, nFrom, nTo);
}

// ---------------- combined gather || mma ----------------
__global__ __launch_bounds__(256, 2) void k_gm(
    const __nv_bfloat16* __restrict__ Gh, const __nv_bfloat16* __restrict__ Gl,
    int layer0, int gFrom, int gTo, int nGB,
    int nMB, int tFrom,
    const __nv_bfloat16* __restrict__ A0h, const __nv_bfloat16* __restrict__ A0l,
    const __nv_bfloat16* __restrict__ A1h, const __nv_bfloat16* __restrict__ A1l,
    int w0, int w1,
    const float* __restrict__ b0, const float* __restrict__ b1,
    const float* __restrict__ r1wl, const float* __restrict__ r1wr,
    int numOps, int do_relu,
    float* __restrict__ fout, int ostride, int ocols,
    __nv_bfloat16* __restrict__ bh_out, __nv_bfloat16* __restrict__ bl_out)
{
    extern __shared__ __align__(16) char smem[];
    int bid = blockIdx.x;
    int tid = threadIdx.x;
    int mmin = (nMB < nGB) ? nMB : nGB;
    int role, idx;
    if (bid < 2 * mmin) { role = bid & 1; idx = bid >> 1; }
    else { idx = bid - mmin; role = (nMB > nGB) ? 0 : 1; }
    // role 0 = mma, role 1 = gather

    if (role == 1) {
        int gw = idx * 8 + (tid >> 5);
        gather_range(Gh, Gl, layer0, gw, nGB * 8, tid & 31, gFrom, gTo);
    } else {
        uint32_t sb = smem_u32(smem);
        int n0 = (tFrom + (idx >> 1)) * TILE_M;
        int c_base = (idx & 1) * 64;
        mma_tile(smem, sb, n0, c_base, tid,
                 A0h, A0l, A1h, A1l, w0, w1, b0, b1, r1wl, r1wr,
                 numOps, do_relu, fout, ostride, ocols, bh_out, bl_out);
    }
}

// ---------------- launch ----------------
extern "C" void kernel_launch(void* const* d_in, const int* in_sizes, int n_in,
                              void* d_out, int out_size) {
    int ix = 0, iWl1 = 1, ibl1 = 2, iWr1 = 3, ibr1 = 4, iWl2 = 5, ibl2 = 6,
        iWr2 = 7, ibr2 = 8, iWo = 9, ibo = 10, iei = 11, icards = 12;
    if (n_in == 13) {
        int w1a[2] = {-1, -1}; int n_w1 = 0;
        int w2a[2] = {-1, -1}; int n_w2 = 0;
        int ba[4] = {-1, -1, -1, -1}; int n_b = 0;
        int f_x = -1, f_Wo = -1, f_bo = -1, f_ei = -1, f_cards = -1;
        for (int i = 0; i < n_in; i++) {
            switch (in_sizes[i]) {
                case (int)((size_t)Nn * FIN): f_x = i; break;
                case HD * K1: if (n_w1 < 2) w1a[n_w1++] = i; break;
                case HD * HD: if (n_w2 < 2) w2a[n_w2++] = i; break;
                case HD:      if (n_b < 4)  ba[n_b++]  = i; break;
                case NCARDS * HD: f_Wo = i; break;
                case NCARDS:      f_bo = i; break;
                case 2 * Ee:      f_ei = i; break;
                case Nn:          f_cards = i; break;
                default: break;
            }
        }
        if (f_x >= 0 && n_w1 == 2 && n_w2 == 2 && n_b == 4 && f_Wo >= 0 &&
            f_bo >= 0 && f_ei >= 0 && f_cards >= 0) {
            ix = f_x; iWl1 = w1a[0]; iWr1 = w1a[1]; iWl2 = w2a[0]; iWr2 = w2a[1];
            ibl1 = ba[0]; ibr1 = ba[1]; ibl2 = ba[2]; ibr2 = ba[3];
            iWo = f_Wo; ibo = f_bo; iei = f_ei; icards = f_cards;
        }
    }

    const float* x   = (const float*)d_in[ix];
    const float* Wl1 = (const float*)d_in[iWl1];
    const float* bl1 = (const float*)d_in[ibl1];
    const float* Wr1 = (const float*)d_in[iWr1];
    const float* br1 = (const float*)d_in[ibr1];
    const float* Wl2 = (const float*)d_in[iWl2];
    const float* bl2 = (const float*)d_in[ibl2];
    const float* Wr2 = (const float*)d_in[iWr2];
    const float* br2 = (const float*)d_in[ibr2];
    const float* Wo  = (const float*)d_in[iWo];
    const float* bo  = (const float*)d_in[ibo];
    const int* ei    = (const int*)d_in[iei];
    const int* cards = (const int*)d_in[icards];
    float* out = (float*)d_out;

    cudaFuncSetAttribute(k_gm, cudaFuncAttributeMaxDynamicSharedMemorySize, SMEM_DYN);

    __nv_bfloat16 *p_b0h, *p_b0l, *p_b1h, *p_b1l, *p_b2h, *p_b2l, *p_bsh, *p_bsl;
    cudaGetSymbolAddress((void**)&p_b0h, g_b0h);
    cudaGetSymbolAddress((void**)&p_b0l, g_b0l);
    cudaGetSymbolAddress((void**)&p_b1h, g_b1h);
    cudaGetSymbolAddress((void**)&p_b1l, g_b1l);
    cudaGetSymbolAddress((void**)&p_b2h, g_b2h);
    cudaGetSymbolAddress((void**)&p_b2l, g_b2l);
    cudaGetSymbolAddress((void**)&p_bsh, g_bsh);
    cudaGetSymbolAddress((void**)&p_bsl, g_bsl);

    // setup
    k_init<<<(Nn + 255) / 256, 256>>>(ei);
    k_setupC<<<NB_CONCAT + NB_DEG + NB_PREP, 256>>>(x, cards, ei, Wl1, Wr1, Wl2, Wr2, Wo);
    k_scanA<<<(Nn + 1023) / 1024, 1024>>>();
    k_place<<<(Ee + 255) / 256, 256>>>(ei);

    // ---- layer 1 ----
    k_gather<<<1024, 256>>>(p_b0h, p_b0l, 1, 0, NSPLIT);
    // mma half-a (op0 = mean agg!) || gather half-b
    k_gm<<<782 + 1024, 256, SMEM_DYN>>>(p_b0h, p_b0l, 1, NSPLIT, Nn, 1024,
                                        782, 0, p_bsh, p_bsl, p_b0h, p_b0l, 0, 1,
                                        bl1, br1, Wl1 + 128, Wr1 + 128, 2, 1,
                                        nullptr, 0, HD, p_b1h, p_b1l);
    // mma half-b
    k_gm<<<782, 256, SMEM_DYN>>>(nullptr, nullptr, 0, 0, 0, 0,
                                 782, TSPLIT, p_bsh, p_bsl, p_b0h, p_b0l, 0, 1,
                                 bl1, br1, Wl1 + 128, Wr1 + 128, 2, 1,
                                 nullptr, 0, HD, p_b1h, p_b1l);

    // ---- layer 2 ----
    k_gather<<<1024, 256>>>(p_b1h, p_b1l, 0, 0, NSPLIT);
    k_gm<<<782 + 1024, 256, SMEM_DYN>>>(p_b1h, p_b1l, 0, NSPLIT, Nn, 1024,
                                        782, 0, p_bsh, p_bsl, p_b1h, p_b1l, 2, 3,
                                        bl2, br2, nullptr, nullptr, 2, 1,
                                        nullptr, 0, HD, p_b2h, p_b2l);
    k_gm<<<782, 256, SMEM_DYN>>>(nullptr, nullptr, 0, 0, 0, 0,
                                 782, TSPLIT, p_bsh, p_bsl, p_b1h, p_b1l, 2, 3,
                                 bl2, br2, nullptr, nullptr, 2, 1,
                                 nullptr, 0, HD, p_b2h, p_b2l);

    // ---- output head ----
    k_gm<<<1564, 256, SMEM_DYN>>>(nullptr, nullptr, 0, 0, 0, 0,
                                  1564, 0, p_b2h, p_b2l, nullptr, nullptr, 4, 4,
                                  bo, nullptr, nullptr, nullptr, 1, 0,
                                  out, NCARDS, NCARDS, nullptr, nullptr);
}

// round 12
// speedup vs baseline: 1.0911x; 1.0911x over previous
#include <cuda_runtime.h>
#include <cuda_bf16.h>
#include <cstdint>

#define Nn 100000
#define Ee 1600000
#define FIN 128
#define K1 129
#define HD 128
#define NCARDS 110
#define TILE_M 128
#define NTILES ((Nn + TILE_M - 1) / TILE_M)   // 782
#define TSPLIT 391
#define NSPLIT (TSPLIT * TILE_M)              // 50048

typedef unsigned int u32;

// ---------------- device scratch ----------------
__device__ __nv_bfloat16 g_b0h[(size_t)Nn * HD], g_b0l[(size_t)Nn * HD];
__device__ __nv_bfloat16 g_b1h[(size_t)Nn * HD], g_b1l[(size_t)Nn * HD];
__device__ __nv_bfloat16 g_b2h[(size_t)Nn * HD], g_b2l[(size_t)Nn * HD];
__device__ __nv_bfloat16 g_bsh[(size_t)Nn * HD], g_bsl[(size_t)Nn * HD];
__device__ float g_cardf[Nn];
__device__ float g_meanC[Nn];
__device__ __nv_bfloat16 g_Whi[5][HD * HD];
__device__ __nv_bfloat16 g_Wlo[5][HD * HD];
__device__ int g_degc[Nn];
__device__ int g_offs[Nn];
__device__ int g_tick[Ee];
__device__ int g_csrc[Ee];
__device__ int g_tot;
__device__ int g_is64;

// ---------------- helpers ----------------
__device__ __forceinline__ unsigned load_ei(const int* p, size_t i, int is64) {
    if (is64) return (unsigned)((const long long*)p)[i];
    return (unsigned)p[i];
}
__device__ __forceinline__ uint32_t smem_u32(const void* p) {
    uint32_t a;
    asm("{ .reg .u64 t; cvta.to.shared.u64 t, %1; cvt.u32.u64 %0, t; }" : "=r"(a) : "l"(p));
    return a;
}
__device__ __forceinline__ u32 cvt2(float a, float b) {
    __nv_bfloat162 t = __floats2bfloat162_rn(a, b);
    return *(u32*)&t;
}
__device__ __forceinline__ void split2(float f0, float f1, u32& hw, u32& lw) {
    __nv_bfloat16 h0 = __float2bfloat16_rn(f0);
    __nv_bfloat16 h1 = __float2bfloat16_rn(f1);
    hw = ((u32)*(unsigned short*)&h1 << 16) | *(unsigned short*)&h0;
    lw = cvt2(f0 - __bfloat162float(h0), f1 - __bfloat162float(h1));
}
__device__ __forceinline__ void acc4(float4& a, uint2 h, uint2 l) {
    float2 h0 = __bfloat1622float2(*(__nv_bfloat162*)&h.x);
    float2 h1 = __bfloat1622float2(*(__nv_bfloat162*)&h.y);
    float2 l0 = __bfloat1622float2(*(__nv_bfloat162*)&l.x);
    float2 l1 = __bfloat1622float2(*(__nv_bfloat162*)&l.y);
    a.x += h0.x + l0.x; a.y += h0.y + l0.y;
    a.z += h1.x + l1.x; a.w += h1.y + l1.y;
}

#define LDM4(r, addr) \
    asm volatile("ldmatrix.sync.aligned.m8n8.x4.shared.b16 {%0,%1,%2,%3}, [%4];" \
                 : "=r"((r)[0]), "=r"((r)[1]), "=r"((r)[2]), "=r"((r)[3]) : "r"(addr))

#define MMA(c, a, bb0, bb1) \
    asm volatile("mma.sync.aligned.m16n8k16.row.col.f32.bf16.bf16.f32 " \
                 "{%0,%1,%2,%3},{%4,%5,%6,%7},{%8,%9},{%0,%1,%2,%3};" \
                 : "+f"((c)[0]), "+f"((c)[1]), "+f"((c)[2]), "+f"((c)[3]) \
                 : "r"((a)[0]), "r"((a)[1]), "r"((a)[2]), "r"((a)[3]), "r"(bb0), "r"(bb1))

#define CPA(dst, src) \
    asm volatile("cp.async.cg.shared.global [%0], [%1], 16;" :: "r"(dst), "l"(src))
#define CPA_COMMIT() asm volatile("cp.async.commit_group;" ::: "memory")
#define CPA_WAIT()   asm volatile("cp.async.wait_group 0;" ::: "memory")

#define RS 272
#define S_AHI 0
#define S_ALO 34816
#define S_WHI 69632
#define S_WLO 87040
#define S_AUX 104448
#define SMEM_DYN (104448 + 3 * 64 * 4)

// ---------------- setup kernels ----------------
__global__ void k_init(const int* __restrict__ ei32) {
    int i = blockIdx.x * blockDim.x + threadIdx.x;
    if (i < Nn) g_degc[i] = 0;
    if (i == 0) {
        g_tot = 0;
        int all_zero = 1;
        for (int w = 1; w < 64; w += 2)
            if (ei32[w] != 0) { all_zero = 0; break; }
        g_is64 = all_zero;
    }
}

#define NB_CONCAT 12500
#define NB_DEG 6250
#define NB_PREP 320

// merged: concat || deghist(+ticket) || prep_w
__global__ void k_setupC(const float* __restrict__ x, const int* __restrict__ cards,
                         const int* __restrict__ ei,
                         const float* __restrict__ Wl1, const float* __restrict__ Wr1,
                         const float* __restrict__ Wl2, const float* __restrict__ Wr2,
                         const float* __restrict__ Wo) {
    int bid = blockIdx.x;
    int tid = threadIdx.x;
    if (bid < NB_CONCAT) {
        int i = bid * 256 + tid;
        if (i >= Nn * 32) return;
        int n = i >> 5, c = (i & 31) * 4;
        float4 v = *(const float4*)(x + (size_t)n * FIN + c);
        uint2 hv, lv;
        split2(v.x, v.y, hv.x, lv.x);
        split2(v.z, v.w, hv.y, lv.y);
        *(uint2*)(g_b0h + (size_t)n * HD + c) = hv;
        *(uint2*)(g_b0l + (size_t)n * HD + c) = lv;
        if ((i & 31) == 0) g_cardf[n] = (float)cards[n];
    } else if (bid < NB_CONCAT + NB_DEG) {
        int e = (bid - NB_CONCAT) * 256 + tid;
        if (e < Ee) {
            unsigned d = load_ei(ei, (size_t)Ee + e, g_is64);
            if (d < Nn) g_tick[e] = atomicAdd(&g_degc[d], 1);
        }
    } else {
        int i = (bid - NB_CONCAT - NB_DEG) * 256 + tid;
        if (i >= 5 * HD * HD) return;
        int op = i / (HD * HD);
        int r = i % (HD * HD);
        int n = r / HD, k = r % HD;
        float v = 0.f;
        if (op == 0) v = Wl1[n * K1 + k];
        else if (op == 1) v = Wr1[n * K1 + k];
        else if (op == 2) v = Wl2[n * HD + k];
        else if (op == 3) v = Wr2[n * HD + k];
        else if (n < NCARDS) v = Wo[n * HD + k];
        __nv_bfloat16 h = __float2bfloat16_rn(v);
        g_Whi[op][r] = h;
        g_Wlo[op][r] = __float2bfloat16_rn(v - __bfloat162float(h));
    }
}

__global__ void k_scanA() {
    __shared__ int sh[1024];
    __shared__ int base;
    int t = threadIdx.x;
    int n = blockIdx.x * 1024 + t;
    int v = (n < Nn) ? g_degc[n] : 0;
    sh[t] = v;
    __syncthreads();
    for (int off = 1; off < 1024; off <<= 1) {
        int add = (t >= off) ? sh[t - off] : 0;
        __syncthreads();
        sh[t] += add;
        __syncthreads();
    }
    if (t == 1023) base = atomicAdd(&g_tot, sh[1023]);
    __syncthreads();
    if (n < Nn) g_offs[n] = base + sh[t] - v;
}

// atomic-free place using precomputed tickets
__global__ void k_place(const int* __restrict__ ei) {
    int e = blockIdx.x * blockDim.x + threadIdx.x;
    if (e < Ee) {
        int is64 = g_is64;
        unsigned s = load_ei(ei, (size_t)e, is64);
        unsigned d = load_ei(ei, (size_t)Ee + e, is64);
        if (s < Nn && d < Nn) {
            int pos = g_offs[d] + g_tick[e];
            if (pos >= 0 && pos < Ee) g_csrc[pos] = (int)s;
        }
    }
}

// ---------------- gather mean-aggregation (split-bf16 src, MLP=4) ----------------
__global__ void k_gather(const __nv_bfloat16* __restrict__ sh_,
                         const __nv_bfloat16* __restrict__ sl_,
                         int layer0, int nFrom, int nTo) {
    int gw = (blockIdx.x * blockDim.x + threadIdx.x) >> 5;
    int lane = threadIdx.x & 31;
    int nw = (gridDim.x * blockDim.x) >> 5;
    for (int n = nFrom + gw; n < nTo; n += nw) {
        int st = g_offs[n];
        int dg = g_degc[n];
        if (st < 0) st = 0;
        if (st + dg > Ee) dg = Ee - st;
        float4 acc = make_float4(0.f, 0.f, 0.f, 0.f);
        float accC = 0.f;
        int i = 0;
        for (; i + 4 <= dg; i += 4) {
            int s0 = g_csrc[st + i];
            int s1 = g_csrc[st + i + 1];
            int s2 = g_csrc[st + i + 2];
            int s3 = g_csrc[st + i + 3];
            uint2 h0 = *(const uint2*)(sh_ + (size_t)s0 * HD + lane * 4);
            uint2 l0 = *(const uint2*)(sl_ + (size_t)s0 * HD + lane * 4);
            uint2 h1 = *(const uint2*)(sh_ + (size_t)s1 * HD + lane * 4);
            uint2 l1 = *(const uint2*)(sl_ + (size_t)s1 * HD + lane * 4);
            uint2 h2 = *(const uint2*)(sh_ + (size_t)s2 * HD + lane * 4);
            uint2 l2 = *(const uint2*)(sl_ + (size_t)s2 * HD + lane * 4);
            uint2 h3 = *(const uint2*)(sh_ + (size_t)s3 * HD + lane * 4);
            uint2 l3 = *(const uint2*)(sl_ + (size_t)s3 * HD + lane * 4);
            acc4(acc, h0, l0); acc4(acc, h1, l1);
            acc4(acc, h2, l2); acc4(acc, h3, l3);
            if (layer0 && lane == 0)
                accC += g_cardf[s0] + g_cardf[s1] + g_cardf[s2] + g_cardf[s3];
        }
        for (; i < dg; ++i) {
            int s = g_csrc[st + i];
            uint2 h = *(const uint2*)(sh_ + (size_t)s * HD + lane * 4);
            uint2 l = *(const uint2*)(sl_ + (size_t)s * HD + lane * 4);
            acc4(acc, h, l);
            if (layer0 && lane == 0) accC += g_cardf[s];
        }
        float di = (dg > 0) ? 1.f / (float)dg : 0.f;
        acc.x *= di; acc.y *= di; acc.z *= di; acc.w *= di;
        uint2 hv, lv;
        split2(acc.x, acc.y, hv.x, lv.x);
        split2(acc.z, acc.w, hv.y, lv.y);
        *(uint2*)(g_bsh + (size_t)n * HD + lane * 4) = hv;
        *(uint2*)(g_bsl + (size_t)n * HD + lane * 4) = lv;
        if (layer0 && lane == 0) g_meanC[n] = accC * di;
    }
}

// ---------------- HMMA fused layer (TILE 128m x 64n) ----------------
__global__ __launch_bounds__(256, 2) void k_mma(
    int tFrom,
    const __nv_bfloat16* __restrict__ A0h, const __nv_bfloat16* __restrict__ A0l,
    const __nv_bfloat16* __restrict__ A1h, const __nv_bfloat16* __restrict__ A1l,
    int w0, int w1,
    const float* __restrict__ b0, const float* __restrict__ b1,
    const float* __restrict__ r1wl, const float* __restrict__ r1wr,
    int numOps, int do_relu,
    float* __restrict__ fout, int ostride, int ocols,
    __nv_bfloat16* __restrict__ bh_out, __nv_bfloat16* __restrict__ bl_out)
{
    extern __shared__ __align__(16) char smem[];
    uint32_t sb = smem_u32(smem);
    float* auxb = (float*)(smem + S_AUX);
    float* auxl = auxb + 64;
    float* auxr = auxl + 64;

    int tid = threadIdx.x;
    int wid = tid >> 5;
    int lane = tid & 31;
    int wr0 = wid * 16;
    int n0 = (tFrom + blockIdx.x) * TILE_M;
    int c_base = blockIdx.y * 64;

    if (tid < 64) {
        int cg = c_base + tid;
        float bs = (cg < ocols) ? b0[cg] : 0.f;
        if (b1 && cg < ocols) bs += b1[cg];
        auxb[tid] = bs;
        auxl[tid] = r1wl ? r1wl[(size_t)cg * K1] : 0.f;
        auxr[tid] = r1wr ? r1wr[(size_t)cg * K1] : 0.f;
    }

    float acc[8][4];
#pragma unroll
    for (int i = 0; i < 8; i++)
#pragma unroll
        for (int j = 0; j < 4; j++) acc[i][j] = 0.f;

    int q = lane >> 3, r8 = lane & 7;
    uint32_t qrow = (uint32_t)((q & 1) * 8 + r8);
    uint32_t qkb = (uint32_t)((q >> 1) * 16);
    uint32_t a_off = (wr0 + qrow) * RS + qkb;

    for (int op = 0; op < numOps; ++op) {
        if (op) __syncthreads();
        const __nv_bfloat16* Ah = op ? A1h : A0h;
        const __nv_bfloat16* Al = op ? A1l : A0l;
        const __nv_bfloat16* Wh = g_Whi[op ? w1 : w0];
        const __nv_bfloat16* Wl = g_Wlo[op ? w1 : w0];

        {
            int r = tid >> 1, half = tid & 1;
            int m = n0 + r;
            uint32_t dh = sb + S_AHI + r * RS + half * 128;
            uint32_t dl = sb + S_ALO + r * RS + half * 128;
            if (m < Nn) {
                const char* srch = (const char*)(Ah + (size_t)m * HD + half * 64);
                const char* srcl = (const char*)(Al + (size_t)m * HD + half * 64);
#pragma unroll
                for (int qq = 0; qq < 8; ++qq) {
                    CPA(dh + qq * 16, srch + qq * 16);
                    CPA(dl + qq * 16, srcl + qq * 16);
                }
            } else {
                uint4 z = make_uint4(0, 0, 0, 0);
#pragma unroll
                for (int qq = 0; qq < 8; ++qq) {
                    *(uint4*)(smem + S_AHI + r * RS + half * 128 + qq * 16) = z;
                    *(uint4*)(smem + S_ALO + r * RS + half * 128 + qq * 16) = z;
                }
            }
        }
        {
            int r = tid >> 2, qtr = tid & 3;
            int nrow = c_base + r;
            const char* srch = (const char*)(Wh + (size_t)nrow * HD + qtr * 32);
            const char* srcl = (const char*)(Wl + (size_t)nrow * HD + qtr * 32);
            uint32_t dh = sb + S_WHI + r * RS + qtr * 64;
            uint32_t dl = sb + S_WLO + r * RS + qtr * 64;
#pragma unroll
            for (int qq = 0; qq < 4; ++qq) {
                CPA(dh + qq * 16, srch + qq * 16);
                CPA(dl + qq * 16, srcl + qq * 16);
            }
        }
        CPA_COMMIT();
        CPA_WAIT();
        __syncthreads();

#pragma unroll
        for (int ks = 0; ks < 8; ++ks) {
            uint32_t kb = ks * 32;
            u32 ah[4], al[4];
            LDM4(ah, sb + S_AHI + a_off + kb);
            LDM4(al, sb + S_ALO + a_off + kb);
#pragma unroll
            for (int p = 0; p < 4; ++p) {
                uint32_t boff = (p * 16 + qrow) * RS + qkb + kb;
                u32 bh[4], bl[4];
                LDM4(bh, sb + S_WHI + boff);
                LDM4(bl, sb + S_WLO + boff);
                MMA(acc[2 * p],     ah, bh[0], bh[2]);
                MMA(acc[2 * p],     ah, bl[0], bl[2]);
                MMA(acc[2 * p],     al, bh[0], bh[2]);
                MMA(acc[2 * p + 1], ah, bh[1], bh[3]);
                MMA(acc[2 * p + 1], ah, bl[1], bl[3]);
                MMA(acc[2 * p + 1], al, bh[1], bh[3]);
            }
        }
    }

    // epilogue
    int l4 = lane >> 2, c2 = (lane & 3) * 2;
    int rA = n0 + wr0 + l4;
    int rB = rA + 8;
    float mcA = 0.f, scA = 0.f, mcB = 0.f, scB = 0.f;
    if (r1wl) {
        if (rA < Nn) { mcA = g_meanC[rA]; scA = g_cardf[rA]; }
        if (rB < Nn) { mcB = g_meanC[rB]; scB = g_cardf[rB]; }
    }
#pragma unroll
    for (int nt = 0; nt < 8; ++nt) {
        int c = nt * 8 + c2;
        int gc = c_base + c;
        float f0 = acc[nt][0] + auxb[c]     + mcA * auxl[c]     + scA * auxr[c];
        float f1 = acc[nt][1] + auxb[c + 1] + mcA * auxl[c + 1] + scA * auxr[c + 1];
        float f2 = acc[nt][2] + auxb[c]     + mcB * auxl[c]     + scB * auxr[c];
        float f3 = acc[nt][3] + auxb[c + 1] + mcB * auxl[c + 1] + scB * auxr[c + 1];
        if (do_relu) {
            f0 = fmaxf(f0, 0.f); f1 = fmaxf(f1, 0.f);
            f2 = fmaxf(f2, 0.f); f3 = fmaxf(f3, 0.f);
        }
        if (fout) {
            if (rA < Nn) {
                if (gc < ocols)     fout[(size_t)rA * ostride + gc]     = f0;
                if (gc + 1 < ocols) fout[(size_t)rA * ostride + gc + 1] = f1;
            }
            if (rB < Nn) {
                if (gc < ocols)     fout[(size_t)rB * ostride + gc]     = f2;
                if (gc + 1 < ocols) fout[(size_t)rB * ostride + gc + 1] = f3;
            }
        }
        if (bh_out) {
            u32 hw, lw;
            if (rA < Nn) {
                split2(f0, f1, hw, lw);
                *(u32*)(bh_out + (size_t)rA * HD + gc) = hw;
                *(u32*)(bl_out + (size_t)rA * HD + gc) = lw;
            }
            if (rB < Nn) {
                split2(f2, f3, hw, lw);
                *(u32*)(bh_out + (size_t)rB * HD + gc) = hw;
                *(u32*)(bl_out + (size_t)rB * HD + gc) = lw;
            }
        }
    }
}

// ---------------- launch ----------------
extern "C" void kernel_launch(void* const* d_in, const int* in_sizes, int n_in,
                              void* d_out, int out_size) {
    int ix = 0, iWl1 = 1, ibl1 = 2, iWr1 = 3, ibr1 = 4, iWl2 = 5, ibl2 = 6,
        iWr2 = 7, ibr2 = 8, iWo = 9, ibo = 10, iei = 11, icards = 12;
    if (n_in == 13) {
        int w1a[2] = {-1, -1}; int n_w1 = 0;
        int w2a[2] = {-1, -1}; int n_w2 = 0;
        int ba[4] = {-1, -1, -1, -1}; int n_b = 0;
        int f_x = -1, f_Wo = -1, f_bo = -1, f_ei = -1, f_cards = -1;
        for (int i = 0; i < n_in; i++) {
            switch (in_sizes[i]) {
                case (int)((size_t)Nn * FIN): f_x = i; break;
                case HD * K1: if (n_w1 < 2) w1a[n_w1++] = i; break;
                case HD * HD: if (n_w2 < 2) w2a[n_w2++] = i; break;
                case HD:      if (n_b < 4)  ba[n_b++]  = i; break;
                case NCARDS * HD: f_Wo = i; break;
                case NCARDS:      f_bo = i; break;
                case 2 * Ee:      f_ei = i; break;
                case Nn:          f_cards = i; break;
                default: break;
            }
        }
        if (f_x >= 0 && n_w1 == 2 && n_w2 == 2 && n_b == 4 && f_Wo >= 0 &&
            f_bo >= 0 && f_ei >= 0 && f_cards >= 0) {
            ix = f_x; iWl1 = w1a[0]; iWr1 = w1a[1]; iWl2 = w2a[0]; iWr2 = w2a[1];
            ibl1 = ba[0]; ibr1 = ba[1]; ibl2 = ba[2]; ibr2 = ba[3];
            iWo = f_Wo; ibo = f_bo; iei = f_ei; icards = f_cards;
        }
    }

    const float* x   = (const float*)d_in[ix];
    const float* Wl1 = (const float*)d_in[iWl1];
    const float* bl1 = (const float*)d_in[ibl1];
    const float* Wr1 = (const float*)d_in[iWr1];
    const float* br1 = (const float*)d_in[ibr1];
    const float* Wl2 = (const float*)d_in[iWl2];
    const float* bl2 = (const float*)d_in[ibl2];
    const float* Wr2 = (const float*)d_in[iWr2];
    const float* br2 = (const float*)d_in[ibr2];
    const float* Wo  = (const float*)d_in[iWo];
    const float* bo  = (const float*)d_in[ibo];
    const int* ei    = (const int*)d_in[iei];
    const int* cards = (const int*)d_in[icards];
    float* out = (float*)d_out;

    cudaFuncSetAttribute(k_mma, cudaFuncAttributeMaxDynamicSharedMemorySize, SMEM_DYN);

    __nv_bfloat16 *p_b0h, *p_b0l, *p_b1h, *p_b1l, *p_b2h, *p_b2l, *p_bsh, *p_bsl;
    cudaGetSymbolAddress((void**)&p_b0h, g_b0h);
    cudaGetSymbolAddress((void**)&p_b0l, g_b0l);
    cudaGetSymbolAddress((void**)&p_b1h, g_b1h);
    cudaGetSymbolAddress((void**)&p_b1l, g_b1l);
    cudaGetSymbolAddress((void**)&p_b2h, g_b2h);
    cudaGetSymbolAddress((void**)&p_b2l, g_b2l);
    cudaGetSymbolAddress((void**)&p_bsh, g_bsh);
    cudaGetSymbolAddress((void**)&p_bsl, g_bsl);

    // fork/join stream + events (created per call; kernel_launch runs only a few times)
    cudaStream_t s1;
    cudaStreamCreateWithFlags(&s1, cudaStreamNonBlocking);
    cudaEvent_t eA, eB, eC, eD;
    cudaEventCreateWithFlags(&eA, cudaEventDisableTiming);
    cudaEventCreateWithFlags(&eB, cudaEventDisableTiming);
    cudaEventCreateWithFlags(&eC, cudaEventDisableTiming);
    cudaEventCreateWithFlags(&eD, cudaEventDisableTiming);

    dim3 mgh(TSPLIT, 2);
    dim3 mgf(NTILES, 2);

    // setup (all on captured default stream)
    k_init<<<(Nn + 255) / 256, 256>>>(ei);
    k_setupC<<<NB_CONCAT + NB_DEG + NB_PREP, 256>>>(x, cards, ei, Wl1, Wr1, Wl2, Wr2, Wo);
    k_scanA<<<(Nn + 1023) / 1024, 1024>>>();
    k_place<<<(Ee + 255) / 256, 256>>>(ei);

    // ---- layer 1: fork gather half-b onto s1 ----
    cudaEventRecord(eA, 0);
    cudaStreamWaitEvent(s1, eA, 0);
    k_gather<<<1024, 256, 0, s1>>>(p_b0h, p_b0l, 1, NSPLIT, Nn);   // half b (overlaps below)
    k_gather<<<1024, 256>>>(p_b0h, p_b0l, 1, 0, NSPLIT);           // half a
    k_mma<<<mgh, 256, SMEM_DYN>>>(0, p_bsh, p_bsl, p_b0h, p_b0l, 0, 1,
                                  bl1, br1, Wl1 + 128, Wr1 + 128, 2, 1,
                                  nullptr, 0, HD, p_b1h, p_b1l);   // tiles 0..390
    cudaEventRecord(eB, s1);
    cudaStreamWaitEvent(0, eB, 0);
    k_mma<<<mgh, 256, SMEM_DYN>>>(TSPLIT, p_bsh, p_bsl, p_b0h, p_b0l, 0, 1,
                                  bl1, br1, Wl1 + 128, Wr1 + 128, 2, 1,
                                  nullptr, 0, HD, p_b1h, p_b1l);   // tiles 391..781

    // ---- layer 2 ----
    cudaEventRecord(eC, 0);
    cudaStreamWaitEvent(s1, eC, 0);
    k_gather<<<1024, 256, 0, s1>>>(p_b1h, p_b1l, 0, NSPLIT, Nn);
    k_gather<<<1024, 256>>>(p_b1h, p_b1l, 0, 0, NSPLIT);
    k_mma<<<mgh, 256, SMEM_DYN>>>(0, p_bsh, p_bsl, p_b1h, p_b1l, 2, 3,
                                  bl2, br2, nullptr, nullptr, 2, 1,
                                  nullptr, 0, HD, p_b2h, p_b2l);
    cudaEventRecord(eD, s1);
    cudaStreamWaitEvent(0, eD, 0);
    k_mma<<<mgh, 256, SMEM_DYN>>>(TSPLIT, p_bsh, p_bsl, p_b1h, p_b1l, 2, 3,
                                  bl2, br2, nullptr, nullptr, 2, 1,
                                  nullptr, 0, HD, p_b2h, p_b2l);

    // ---- output head ----
    k_mma<<<mgf, 256, SMEM_DYN>>>(0, p_b2h, p_b2l, nullptr, nullptr, 4, 4,
                                  bo, nullptr, nullptr, nullptr, 1, 0,
                                  out, NCARDS, NCARDS, nullptr, nullptr);
}

// round 13
// speedup vs baseline: 1.1510x; 1.0549x over previous
#include <cuda_runtime.h>
#include <cuda_bf16.h>
#include <cstdint>

#define Nn 100000
#define Ee 1600000
#define FIN 128
#define K1 129
#define HD 128
#define NCARDS 110
#define TILE_M 128
#define NTILES ((Nn + TILE_M - 1) / TILE_M)   // 782

typedef unsigned int u32;

// ---------------- device scratch ----------------
__device__ __nv_bfloat16 g_b0h[(size_t)Nn * HD], g_b0l[(size_t)Nn * HD];
__device__ __nv_bfloat16 g_b1h[(size_t)Nn * HD], g_b1l[(size_t)Nn * HD];
__device__ __nv_bfloat16 g_b2h[(size_t)Nn * HD], g_b2l[(size_t)Nn * HD];
__device__ __nv_bfloat16 g_bsh[(size_t)Nn * HD], g_bsl[(size_t)Nn * HD];
__device__ float g_cardf[Nn];
__device__ float g_meanC[Nn];
__device__ __nv_bfloat16 g_Whi[5][HD * HD];
__device__ __nv_bfloat16 g_Wlo[5][HD * HD];
__device__ int g_degc[Nn];
__device__ int g_offs[Nn];
__device__ int g_tick[Ee];
__device__ int g_csrc[Ee];
__device__ int g_tot;
__device__ int g_is64;

// ---------------- helpers ----------------
__device__ __forceinline__ unsigned load_ei(const int* p, size_t i, int is64) {
    if (is64) return (unsigned)((const long long*)p)[i];
    return (unsigned)p[i];
}
__device__ __forceinline__ uint32_t smem_u32(const void* p) {
    uint32_t a;
    asm("{ .reg .u64 t; cvta.to.shared.u64 t, %1; cvt.u32.u64 %0, t; }" : "=r"(a) : "l"(p));
    return a;
}
__device__ __forceinline__ u32 cvt2(float a, float b) {
    __nv_bfloat162 t = __floats2bfloat162_rn(a, b);
    return *(u32*)&t;
}
__device__ __forceinline__ void split2(float f0, float f1, u32& hw, u32& lw) {
    __nv_bfloat16 h0 = __float2bfloat16_rn(f0);
    __nv_bfloat16 h1 = __float2bfloat16_rn(f1);
    hw = ((u32)*(unsigned short*)&h1 << 16) | *(unsigned short*)&h0;
    lw = cvt2(f0 - __bfloat162float(h0), f1 - __bfloat162float(h1));
}
__device__ __forceinline__ void acc4(float4& a, uint2 h, uint2 l) {
    float2 h0 = __bfloat1622float2(*(__nv_bfloat162*)&h.x);
    float2 h1 = __bfloat1622float2(*(__nv_bfloat162*)&h.y);
    float2 l0 = __bfloat1622float2(*(__nv_bfloat162*)&l.x);
    float2 l1 = __bfloat1622float2(*(__nv_bfloat162*)&l.y);
    a.x += h0.x + l0.x; a.y += h0.y + l0.y;
    a.z += h1.x + l1.x; a.w += h1.y + l1.y;
}

#define LDM4(r, addr) \
    asm volatile("ldmatrix.sync.aligned.m8n8.x4.shared.b16 {%0,%1,%2,%3}, [%4];" \
                 : "=r"((r)[0]), "=r"((r)[1]), "=r"((r)[2]), "=r"((r)[3]) : "r"(addr))

#define MMA(c, a, bb0, bb1) \
    asm volatile("mma.sync.aligned.m16n8k16.row.col.f32.bf16.bf16.f32 " \
                 "{%0,%1,%2,%3},{%4,%5,%6,%7},{%8,%9},{%0,%1,%2,%3};" \
                 : "+f"((c)[0]), "+f"((c)[1]), "+f"((c)[2]), "+f"((c)[3]) \
                 : "r"((a)[0]), "r"((a)[1]), "r"((a)[2]), "r"((a)[3]), "r"(bb0), "r"(bb1))

#define CPA(dst, src) \
    asm volatile("cp.async.cg.shared.global [%0], [%1], 16;" :: "r"(dst), "l"(src))
#define CPA_COMMIT() asm volatile("cp.async.commit_group;" ::: "memory")
#define CPA_WAIT()   asm volatile("cp.async.wait_group 0;" ::: "memory")

#define RS 272
#define S_AHI 0
#define S_ALO 34816
#define S_WHI 69632
#define S_WLO 87040
#define S_AUX 104448
#define SMEM_DYN (104448 + 3 * 64 * 4)

// ---------------- setup ----------------
__global__ void k_init(const int* __restrict__ ei32) {
    int i = blockIdx.x * blockDim.x + threadIdx.x;
    if (i < Nn) g_degc[i] = 0;
    if (i == 0) {
        g_tot = 0;
        int all_zero = 1;
        for (int w = 1; w < 64; w += 2)
            if (ei32[w] != 0) { all_zero = 0; break; }
        g_is64 = all_zero;
    }
}

#define NB_CONCAT 12500
#define NB_DEG 6250
#define NB_PREP 320

// merged: concat || deghist(+ticket) || prep_w
__global__ void k_setupC(const float* __restrict__ x, const int* __restrict__ cards,
                         const int* __restrict__ ei,
                         const float* __restrict__ Wl1, const float* __restrict__ Wr1,
                         const float* __restrict__ Wl2, const float* __restrict__ Wr2,
                         const float* __restrict__ Wo) {
    int bid = blockIdx.x;
    int tid = threadIdx.x;
    if (bid < NB_CONCAT) {
        int i = bid * 256 + tid;
        if (i >= Nn * 32) return;
        int n = i >> 5, c = (i & 31) * 4;
        float4 v = *(const float4*)(x + (size_t)n * FIN + c);
        uint2 hv, lv;
        split2(v.x, v.y, hv.x, lv.x);
        split2(v.z, v.w, hv.y, lv.y);
        *(uint2*)(g_b0h + (size_t)n * HD + c) = hv;
        *(uint2*)(g_b0l + (size_t)n * HD + c) = lv;
        if ((i & 31) == 0) g_cardf[n] = (float)cards[n];
    } else if (bid < NB_CONCAT + NB_DEG) {
        int e = (bid - NB_CONCAT) * 256 + tid;
        if (e < Ee) {
            unsigned d = load_ei(ei, (size_t)Ee + e, g_is64);
            if (d < Nn) g_tick[e] = atomicAdd(&g_degc[d], 1);
        }
    } else {
        int i = (bid - NB_CONCAT - NB_DEG) * 256 + tid;
        if (i >= 5 * HD * HD) return;
        int op = i / (HD * HD);
        int r = i % (HD * HD);
        int n = r / HD, k = r % HD;
        float v = 0.f;
        if (op == 0) v = Wl1[n * K1 + k];
        else if (op == 1) v = Wr1[n * K1 + k];
        else if (op == 2) v = Wl2[n * HD + k];
        else if (op == 3) v = Wr2[n * HD + k];
        else if (n < NCARDS) v = Wo[n * HD + k];
        __nv_bfloat16 h = __float2bfloat16_rn(v);
        g_Whi[op][r] = h;
        g_Wlo[op][r] = __float2bfloat16_rn(v - __bfloat162float(h));
    }
}

__global__ void k_scanA() {
    __shared__ int sh[1024];
    __shared__ int base;
    int t = threadIdx.x;
    int n = blockIdx.x * 1024 + t;
    int v = (n < Nn) ? g_degc[n] : 0;
    sh[t] = v;
    __syncthreads();
    for (int off = 1; off < 1024; off <<= 1) {
        int add = (t >= off) ? sh[t - off] : 0;
        __syncthreads();
        sh[t] += add;
        __syncthreads();
    }
    if (t == 1023) base = atomicAdd(&g_tot, sh[1023]);
    __syncthreads();
    if (n < Nn) g_offs[n] = base + sh[t] - v;
}

// atomic-free place using precomputed tickets
__global__ void k_place(const int* __restrict__ ei) {
    int e = blockIdx.x * blockDim.x + threadIdx.x;
    if (e < Ee) {
        int is64 = g_is64;
        unsigned s = load_ei(ei, (size_t)e, is64);
        unsigned d = load_ei(ei, (size_t)Ee + e, is64);
        if (s < Nn && d < Nn) {
            int pos = g_offs[d] + g_tick[e];
            if (pos >= 0 && pos < Ee) g_csrc[pos] = (int)s;
        }
    }
}

// ---------------- gather mean-aggregation (split-bf16 src, MLP=4) ----------------
__global__ void k_gather(const __nv_bfloat16* __restrict__ sh_,
                         const __nv_bfloat16* __restrict__ sl_, int layer0) {
    int gw = (blockIdx.x * blockDim.x + threadIdx.x) >> 5;
    int lane = threadIdx.x & 31;
    int nw = (gridDim.x * blockDim.x) >> 5;
    for (int n = gw; n < Nn; n += nw) {
        int st = g_offs[n];
        int dg = g_degc[n];
        if (st < 0) st = 0;
        if (st + dg > Ee) dg = Ee - st;
        float4 acc = make_float4(0.f, 0.f, 0.f, 0.f);
        float accC = 0.f;
        int i = 0;
        for (; i + 4 <= dg; i += 4) {
            int s0 = g_csrc[st + i];
            int s1 = g_csrc[st + i + 1];
            int s2 = g_csrc[st + i + 2];
            int s3 = g_csrc[st + i + 3];
            uint2 h0 = *(const uint2*)(sh_ + (size_t)s0 * HD + lane * 4);
            uint2 l0 = *(const uint2*)(sl_ + (size_t)s0 * HD + lane * 4);
            uint2 h1 = *(const uint2*)(sh_ + (size_t)s1 * HD + lane * 4);
            uint2 l1 = *(const uint2*)(sl_ + (size_t)s1 * HD + lane * 4);
            uint2 h2 = *(const uint2*)(sh_ + (size_t)s2 * HD + lane * 4);
            uint2 l2 = *(const uint2*)(sl_ + (size_t)s2 * HD + lane * 4);
            uint2 h3 = *(const uint2*)(sh_ + (size_t)s3 * HD + lane * 4);
            uint2 l3 = *(const uint2*)(sl_ + (size_t)s3 * HD + lane * 4);
            acc4(acc, h0, l0); acc4(acc, h1, l1);
            acc4(acc, h2, l2); acc4(acc, h3, l3);
            if (layer0 && lane == 0)
                accC += g_cardf[s0] + g_cardf[s1] + g_cardf[s2] + g_cardf[s3];
        }
        for (; i < dg; ++i) {
            int s = g_csrc[st + i];
            uint2 h = *(const uint2*)(sh_ + (size_t)s * HD + lane * 4);
            uint2 l = *(const uint2*)(sl_ + (size_t)s * HD + lane * 4);
            acc4(acc, h, l);
            if (layer0 && lane == 0) accC += g_cardf[s];
        }
        float di = (dg > 0) ? 1.f / (float)dg : 0.f;
        acc.x *= di; acc.y *= di; acc.z *= di; acc.w *= di;
        uint2 hv, lv;
        split2(acc.x, acc.y, hv.x, lv.x);
        split2(acc.z, acc.w, hv.y, lv.y);
        *(uint2*)(g_bsh + (size_t)n * HD + lane * 4) = hv;
        *(uint2*)(g_bsl + (size_t)n * HD + lane * 4) = lv;
        if (layer0 && lane == 0) g_meanC[n] = accC * di;
    }
}

// ---------------- HMMA fused layer (TILE 128m x 64n) ----------------
__global__ __launch_bounds__(256, 2) void k_mma(
    const __nv_bfloat16* __restrict__ A0h, const __nv_bfloat16* __restrict__ A0l,
    const __nv_bfloat16* __restrict__ A1h, const __nv_bfloat16* __restrict__ A1l,
    int w0, int w1,
    const float* __restrict__ b0, const float* __restrict__ b1,
    const float* __restrict__ r1wl, const float* __restrict__ r1wr,
    int numOps, int do_relu,
    float* __restrict__ fout, int ostride, int ocols,
    __nv_bfloat16* __restrict__ bh_out, __nv_bfloat16* __restrict__ bl_out)
{
    extern __shared__ __align__(16) char smem[];
    uint32_t sb = smem_u32(smem);
    float* auxb = (float*)(smem + S_AUX);
    float* auxl = auxb + 64;
    float* auxr = auxl + 64;

    int tid = threadIdx.x;
    int wid = tid >> 5;
    int lane = tid & 31;
    int wr0 = wid * 16;
    int n0 = blockIdx.x * TILE_M;
    int c_base = blockIdx.y * 64;

    if (tid < 64) {
        int cg = c_base + tid;
        float bs = (cg < ocols) ? b0[cg] : 0.f;
        if (b1 && cg < ocols) bs += b1[cg];
        auxb[tid] = bs;
        auxl[tid] = r1wl ? r1wl[(size_t)cg * K1] : 0.f;
        auxr[tid] = r1wr ? r1wr[(size_t)cg * K1] : 0.f;
    }

    float acc[8][4];
#pragma unroll
    for (int i = 0; i < 8; i++)
#pragma unroll
        for (int j = 0; j < 4; j++) acc[i][j] = 0.f;

    int q = lane >> 3, r8 = lane & 7;
    uint32_t qrow = (uint32_t)((q & 1) * 8 + r8);
    uint32_t qkb = (uint32_t)((q >> 1) * 16);
    uint32_t a_off = (wr0 + qrow) * RS + qkb;

    for (int op = 0; op < numOps; ++op) {
        if (op) __syncthreads();
        const __nv_bfloat16* Ah = op ? A1h : A0h;
        const __nv_bfloat16* Al = op ? A1l : A0l;
        const __nv_bfloat16* Wh = g_Whi[op ? w1 : w0];
        const __nv_bfloat16* Wl = g_Wlo[op ? w1 : w0];

        {
            int r = tid >> 1, half = tid & 1;
            int m = n0 + r;
            uint32_t dh = sb + S_AHI + r * RS + half * 128;
            uint32_t dl = sb + S_ALO + r * RS + half * 128;
            if (m < Nn) {
                const char* srch = (const char*)(Ah + (size_t)m * HD + half * 64);
                const char* srcl = (const char*)(Al + (size_t)m * HD + half * 64);
#pragma unroll
                for (int qq = 0; qq < 8; ++qq) {
                    CPA(dh + qq * 16, srch + qq * 16);
                    CPA(dl + qq * 16, srcl + qq * 16);
                }
            } else {
                uint4 z = make_uint4(0, 0, 0, 0);
#pragma unroll
                for (int qq = 0; qq < 8; ++qq) {
                    *(uint4*)(smem + S_AHI + r * RS + half * 128 + qq * 16) = z;
                    *(uint4*)(smem + S_ALO + r * RS + half * 128 + qq * 16) = z;
                }
            }
        }
        {
            int r = tid >> 2, qtr = tid & 3;
            int nrow = c_base + r;
            const char* srch = (const char*)(Wh + (size_t)nrow * HD + qtr * 32);
            const char* srcl = (const char*)(Wl + (size_t)nrow * HD + qtr * 32);
            uint32_t dh = sb + S_WHI + r * RS + qtr * 64;
            uint32_t dl = sb + S_WLO + r * RS + qtr * 64;
#pragma unroll
            for (int qq = 0; qq < 4; ++qq) {
                CPA(dh + qq * 16, srch + qq * 16);
                CPA(dl + qq * 16, srcl + qq * 16);
            }
        }
        CPA_COMMIT();
        CPA_WAIT();
        __syncthreads();

#pragma unroll
        for (int ks = 0; ks < 8; ++ks) {
            uint32_t kb = ks * 32;
            u32 ah[4], al[4];
            LDM4(ah, sb + S_AHI + a_off + kb);
            LDM4(al, sb + S_ALO + a_off + kb);
#pragma unroll
            for (int p = 0; p < 4; ++p) {
                uint32_t boff = (p * 16 + qrow) * RS + qkb + kb;
                u32 bh[4], bl[4];
                LDM4(bh, sb + S_WHI + boff);
                LDM4(bl, sb + S_WLO + boff);
                MMA(acc[2 * p],     ah, bh[0], bh[2]);
                MMA(acc[2 * p],     ah, bl[0], bl[2]);
                MMA(acc[2 * p],     al, bh[0], bh[2]);
                MMA(acc[2 * p + 1], ah, bh[1], bh[3]);
                MMA(acc[2 * p + 1], ah, bl[1], bl[3]);
                MMA(acc[2 * p + 1], al, bh[1], bh[3]);
            }
        }
    }

    // epilogue
    int l4 = lane >> 2, c2 = (lane & 3) * 2;
    int rA = n0 + wr0 + l4;
    int rB = rA + 8;
    float mcA = 0.f, scA = 0.f, mcB = 0.f, scB = 0.f;
    if (r1wl) {
        if (rA < Nn) { mcA = g_meanC[rA]; scA = g_cardf[rA]; }
        if (rB < Nn) { mcB = g_meanC[rB]; scB = g_cardf[rB]; }
    }
#pragma unroll
    for (int nt = 0; nt < 8; ++nt) {
        int c = nt * 8 + c2;
        int gc = c_base + c;
        float f0 = acc[nt][0] + auxb[c]     + mcA * auxl[c]     + scA * auxr[c];
        float f1 = acc[nt][1] + auxb[c + 1] + mcA * auxl[c + 1] + scA * auxr[c + 1];
        float f2 = acc[nt][2] + auxb[c]     + mcB * auxl[c]     + scB * auxr[c];
        float f3 = acc[nt][3] + auxb[c + 1] + mcB * auxl[c + 1] + scB * auxr[c + 1];
        if (do_relu) {
            f0 = fmaxf(f0, 0.f); f1 = fmaxf(f1, 0.f);
            f2 = fmaxf(f2, 0.f); f3 = fmaxf(f3, 0.f);
        }
        if (fout) {
            if (rA < Nn) {
                if (gc < ocols)     fout[(size_t)rA * ostride + gc]     = f0;
                if (gc + 1 < ocols) fout[(size_t)rA * ostride + gc + 1] = f1;
            }
            if (rB < Nn) {
                if (gc < ocols)     fout[(size_t)rB * ostride + gc]     = f2;
                if (gc + 1 < ocols) fout[(size_t)rB * ostride + gc + 1] = f3;
            }
        }
        if (bh_out) {
            u32 hw, lw;
            if (rA < Nn) {
                split2(f0, f1, hw, lw);
                *(u32*)(bh_out + (size_t)rA * HD + gc) = hw;
                *(u32*)(bl_out + (size_t)rA * HD + gc) = lw;
            }
            if (rB < Nn) {
                split2(f2, f3, hw, lw);
                *(u32*)(bh_out + (size_t)rB * HD + gc) = hw;
                *(u32*)(bl_out + (size_t)rB * HD + gc) = lw;
            }
        }
    }
}

// ---------------- launch ----------------
extern "C" void kernel_launch(void* const* d_in, const int* in_sizes, int n_in,
                              void* d_out, int out_size) {
    int ix = 0, iWl1 = 1, ibl1 = 2, iWr1 = 3, ibr1 = 4, iWl2 = 5, ibl2 = 6,
        iWr2 = 7, ibr2 = 8, iWo = 9, ibo = 10, iei = 11, icards = 12;
    if (n_in == 13) {
        int w1a[2] = {-1, -1}; int n_w1 = 0;
        int w2a[2] = {-1, -1}; int n_w2 = 0;
        int ba[4] = {-1, -1, -1, -1}; int n_b = 0;
        int f_x = -1, f_Wo = -1, f_bo = -1, f_ei = -1, f_cards = -1;
        for (int i = 0; i < n_in; i++) {
            switch (in_sizes[i]) {
                case (int)((size_t)Nn * FIN): f_x = i; break;
                case HD * K1: if (n_w1 < 2) w1a[n_w1++] = i; break;
                case HD * HD: if (n_w2 < 2) w2a[n_w2++] = i; break;
                case HD:      if (n_b < 4)  ba[n_b++]  = i; break;
                case NCARDS * HD: f_Wo = i; break;
                case NCARDS:      f_bo = i; break;
                case 2 * Ee:      f_ei = i; break;
                case Nn:          f_cards = i; break;
                default: break;
            }
        }
        if (f_x >= 0 && n_w1 == 2 && n_w2 == 2 && n_b == 4 && f_Wo >= 0 &&
            f_bo >= 0 && f_ei >= 0 && f_cards >= 0) {
            ix = f_x; iWl1 = w1a[0]; iWr1 = w1a[1]; iWl2 = w2a[0]; iWr2 = w2a[1];
            ibl1 = ba[0]; ibr1 = ba[1]; ibl2 = ba[2]; ibr2 = ba[3];
            iWo = f_Wo; ibo = f_bo; iei = f_ei; icards = f_cards;
        }
    }

    const float* x   = (const float*)d_in[ix];
    const float* Wl1 = (const float*)d_in[iWl1];
    const float* bl1 = (const float*)d_in[ibl1];
    const float* Wr1 = (const float*)d_in[iWr1];
    const float* br1 = (const float*)d_in[ibr1];
    const float* Wl2 = (const float*)d_in[iWl2];
    const float* bl2 = (const float*)d_in[ibl2];
    const float* Wr2 = (const float*)d_in[iWr2];
    const float* br2 = (const float*)d_in[ibr2];
    const float* Wo  = (const float*)d_in[iWo];
    const float* bo  = (const float*)d_in[ibo];
    const int* ei    = (const int*)d_in[iei];
    const int* cards = (const int*)d_in[icards];
    float* out = (float*)d_out;

    cudaFuncSetAttribute(k_mma, cudaFuncAttributeMaxDynamicSharedMemorySize, SMEM_DYN);

    __nv_bfloat16 *p_b0h, *p_b0l, *p_b1h, *p_b1l, *p_b2h, *p_b2l, *p_bsh, *p_bsl;
    cudaGetSymbolAddress((void**)&p_b0h, g_b0h);
    cudaGetSymbolAddress((void**)&p_b0l, g_b0l);
    cudaGetSymbolAddress((void**)&p_b1h, g_b1h);
    cudaGetSymbolAddress((void**)&p_b1l, g_b1l);
    cudaGetSymbolAddress((void**)&p_b2h, g_b2h);
    cudaGetSymbolAddress((void**)&p_b2l, g_b2l);
    cudaGetSymbolAddress((void**)&p_bsh, g_bsh);
    cudaGetSymbolAddress((void**)&p_bsl, g_bsl);

    dim3 mg(NTILES, 2);

    k_init<<<(Nn + 255) / 256, 256>>>(ei);
    k_setupC<<<NB_CONCAT + NB_DEG + NB_PREP, 256>>>(x, cards, ei, Wl1, Wr1, Wl2, Wr2, Wo);
    k_scanA<<<(Nn + 1023) / 1024, 1024>>>();
    k_place<<<(Ee + 255) / 256, 256>>>(ei);

    // layer 1
    k_gather<<<2048, 256>>>(p_b0h, p_b0l, 1);
    k_mma<<<mg, 256, SMEM_DYN>>>(p_bsh, p_bsl, p_b0h, p_b0l, 0, 1, bl1, br1,
                                 Wl1 + 128, Wr1 + 128, 2, 1,
                                 nullptr, 0, HD, p_b1h, p_b1l);

    // layer 2
    k_gather<<<2048, 256>>>(p_b1h, p_b1l, 0);
    k_mma<<<mg, 256, SMEM_DYN>>>(p_bsh, p_bsl, p_b1h, p_b1l, 2, 3, bl2, br2,
                                 nullptr, nullptr, 2, 1,
                                 nullptr, 0, HD, p_b2h, p_b2l);

    // output head
    k_mma<<<mg, 256, SMEM_DYN>>>(p_b2h, p_b2l, nullptr, nullptr, 4, 4, bo, nullptr,
                                 nullptr, nullptr, 1, 0,
                                 out, NCARDS, NCARDS, nullptr, nullptr);
}

// round 14
// speedup vs baseline: 1.3041x; 1.1330x over previous
#include <cuda_runtime.h>
#include <cuda_fp16.h>
#include <cstdint>

#define Nn 100000
#define Ee 1600000
#define FIN 128
#define K1 129
#define HD 128
#define NCARDS 110
#define TILE_M 128
#define NTILES ((Nn + TILE_M - 1) / TILE_M)   // 782

typedef unsigned int u32;

// ---------------- device scratch (fp16 split: v = hi + lo) ----------------
__device__ __half g_b0h[(size_t)Nn * HD], g_b0l[(size_t)Nn * HD];
__device__ __half g_b1h[(size_t)Nn * HD], g_b1l[(size_t)Nn * HD];
__device__ __half g_b2h[(size_t)Nn * HD], g_b2l[(size_t)Nn * HD];
__device__ __half g_bsh[(size_t)Nn * HD], g_bsl[(size_t)Nn * HD];
__device__ float g_cardf[Nn];
__device__ float g_meanC[Nn];
// fp16 weights (hi only): 0=Wl1,1=Wr1,2=Wl2,3=Wr2,4=Wo (padded [128,128], row-major [n][k])
__device__ __half g_Whi[5][HD * HD];
__device__ int g_degc[Nn];
__device__ int g_offs[Nn];
__device__ int g_tick[Ee];
__device__ int g_csrc[Ee];
__device__ int g_tot;
__device__ int g_is64;

// ---------------- helpers ----------------
__device__ __forceinline__ unsigned load_ei(const int* p, size_t i, int is64) {
    if (is64) return (unsigned)((const long long*)p)[i];
    return (unsigned)p[i];
}
__device__ __forceinline__ uint32_t smem_u32(const void* p) {
    uint32_t a;
    asm("{ .reg .u64 t; cvta.to.shared.u64 t, %1; cvt.u32.u64 %0, t; }" : "=r"(a) : "l"(p));
    return a;
}
// split pair (f0,f1) -> fp16 hi word, fp16 lo word
__device__ __forceinline__ void split2(float f0, float f1, u32& hw, u32& lw) {
    __half h0 = __float2half_rn(f0);
    __half h1 = __float2half_rn(f1);
    __half2 hh = __halves2half2(h0, h1);
    __half2 ll = __floats2half2_rn(f0 - __half2float(h0), f1 - __half2float(h1));
    hw = *(u32*)&hh;
    lw = *(u32*)&ll;
}
// accumulate 4 floats from split fp16 uint2 pair
__device__ __forceinline__ void acc4(float4& a, uint2 h, uint2 l) {
    float2 h0 = __half22float2(*(__half2*)&h.x);
    float2 h1 = __half22float2(*(__half2*)&h.y);
    float2 l0 = __half22float2(*(__half2*)&l.x);
    float2 l1 = __half22float2(*(__half2*)&l.y);
    a.x += h0.x + l0.x; a.y += h0.y + l0.y;
    a.z += h1.x + l1.x; a.w += h1.y + l1.y;
}

#define LDM4(r, addr) \
    asm volatile("ldmatrix.sync.aligned.m8n8.x4.shared.b16 {%0,%1,%2,%3}, [%4];" \
                 : "=r"((r)[0]), "=r"((r)[1]), "=r"((r)[2]), "=r"((r)[3]) : "r"(addr))

#define MMA(c, a, bb0, bb1) \
    asm volatile("mma.sync.aligned.m16n8k16.row.col.f32.f16.f16.f32 " \
                 "{%0,%1,%2,%3},{%4,%5,%6,%7},{%8,%9},{%0,%1,%2,%3};" \
                 : "+f"((c)[0]), "+f"((c)[1]), "+f"((c)[2]), "+f"((c)[3]) \
                 : "r"((a)[0]), "r"((a)[1]), "r"((a)[2]), "r"((a)[3]), "r"(bb0), "r"(bb1))

#define CPA(dst, src) \
    asm volatile("cp.async.cg.shared.global [%0], [%1], 16;" :: "r"(dst), "l"(src))
#define CPA_COMMIT() asm volatile("cp.async.commit_group;" ::: "memory")
#define CPA_WAIT()   asm volatile("cp.async.wait_group 0;" ::: "memory")

// smem; row stride 272B = 17*16 -> conflict-free ldmatrix
#define RS 272
#define S_AHI 0
#define S_ALO 34816
#define S_WHI 69632
#define S_AUX 87040             // auxb[64], auxl[64], auxr[64] floats
#define SMEM_DYN (87040 + 3 * 64 * 4)

// ---------------- setup ----------------
__global__ void k_init(const int* __restrict__ ei32) {
    int i = blockIdx.x * blockDim.x + threadIdx.x;
    if (i < Nn) g_degc[i] = 0;
    if (i == 0) {
        g_tot = 0;
        int all_zero = 1;
        for (int w = 1; w < 64; w += 2)
            if (ei32[w] != 0) { all_zero = 0; break; }
        g_is64 = all_zero;
    }
}

#define NB_CONCAT 12500
#define NB_DEG 6250
#define NB_PREP 320

// merged: concat || deghist(+ticket) || prep_w
__global__ void k_setupC(const float* __restrict__ x, const int* __restrict__ cards,
                         const int* __restrict__ ei,
                         const float* __restrict__ Wl1, const float* __restrict__ Wr1,
                         const float* __restrict__ Wl2, const float* __restrict__ Wr2,
                         const float* __restrict__ Wo) {
    int bid = blockIdx.x;
    int tid = threadIdx.x;
    if (bid < NB_CONCAT) {
        int i = bid * 256 + tid;
        if (i >= Nn * 32) return;
        int n = i >> 5, c = (i & 31) * 4;
        float4 v = *(const float4*)(x + (size_t)n * FIN + c);
        uint2 hv, lv;
        split2(v.x, v.y, hv.x, lv.x);
        split2(v.z, v.w, hv.y, lv.y);
        *(uint2*)(g_b0h + (size_t)n * HD + c) = hv;
        *(uint2*)(g_b0l + (size_t)n * HD + c) = lv;
        if ((i & 31) == 0) g_cardf[n] = (float)cards[n];
    } else if (bid < NB_CONCAT + NB_DEG) {
        int e = (bid - NB_CONCAT) * 256 + tid;
        if (e < Ee) {
            unsigned d = load_ei(ei, (size_t)Ee + e, g_is64);
            if (d < Nn) g_tick[e] = atomicAdd(&g_degc[d], 1);
        }
    } else {
        int i = (bid - NB_CONCAT - NB_DEG) * 256 + tid;
        if (i >= 5 * HD * HD) return;
        int op = i / (HD * HD);
        int r = i % (HD * HD);
        int n = r / HD, k = r % HD;
        float v = 0.f;
        if (op == 0) v = Wl1[n * K1 + k];
        else if (op == 1) v = Wr1[n * K1 + k];
        else if (op == 2) v = Wl2[n * HD + k];
        else if (op == 3) v = Wr2[n * HD + k];
        else if (n < NCARDS) v = Wo[n * HD + k];
        g_Whi[op][r] = __float2half_rn(v);
    }
}

__global__ void k_scanA() {
    __shared__ int sh[1024];
    __shared__ int base;
    int t = threadIdx.x;
    int n = blockIdx.x * 1024 + t;
    int v = (n < Nn) ? g_degc[n] : 0;
    sh[t] = v;
    __syncthreads();
    for (int off = 1; off < 1024; off <<= 1) {
        int add = (t >= off) ? sh[t - off] : 0;
        __syncthreads();
        sh[t] += add;
        __syncthreads();
    }
    if (t == 1023) base = atomicAdd(&g_tot, sh[1023]);
    __syncthreads();
    if (n < Nn) g_offs[n] = base + sh[t] - v;
}

// atomic-free place using precomputed tickets
__global__ void k_place(const int* __restrict__ ei) {
    int e = blockIdx.x * blockDim.x + threadIdx.x;
    if (e < Ee) {
        int is64 = g_is64;
        unsigned s = load_ei(ei, (size_t)e, is64);
        unsigned d = load_ei(ei, (size_t)Ee + e, is64);
        if (s < Nn && d < Nn) {
            int pos = g_offs[d] + g_tick[e];
            if (pos >= 0 && pos < Ee) g_csrc[pos] = (int)s;
        }
    }
}

// ---------------- gather mean-aggregation (split-fp16 src, MLP=4) ----------------
__global__ void k_gather(const __half* __restrict__ sh_,
                         const __half* __restrict__ sl_, int layer0) {
    int gw = (blockIdx.x * blockDim.x + threadIdx.x) >> 5;
    int lane = threadIdx.x & 31;
    int nw = (gridDim.x * blockDim.x) >> 5;
    for (int n = gw; n < Nn; n += nw) {
        int st = g_offs[n];
        int dg = g_degc[n];
        if (st < 0) st = 0;
        if (st + dg > Ee) dg = Ee - st;
        float4 acc = make_float4(0.f, 0.f, 0.f, 0.f);
        float accC = 0.f;
        int i = 0;
        for (; i + 4 <= dg; i += 4) {
            int s0 = g_csrc[st + i];
            int s1 = g_csrc[st + i + 1];
            int s2 = g_csrc[st + i + 2];
            int s3 = g_csrc[st + i + 3];
            uint2 h0 = *(const uint2*)(sh_ + (size_t)s0 * HD + lane * 4);
            uint2 l0 = *(const uint2*)(sl_ + (size_t)s0 * HD + lane * 4);
            uint2 h1 = *(const uint2*)(sh_ + (size_t)s1 * HD + lane * 4);
            uint2 l1 = *(const uint2*)(sl_ + (size_t)s1 * HD + lane * 4);
            uint2 h2 = *(const uint2*)(sh_ + (size_t)s2 * HD + lane * 4);
            uint2 l2 = *(const uint2*)(sl_ + (size_t)s2 * HD + lane * 4);
            uint2 h3 = *(const uint2*)(sh_ + (size_t)s3 * HD + lane * 4);
            uint2 l3 = *(const uint2*)(sl_ + (size_t)s3 * HD + lane * 4);
            acc4(acc, h0, l0); acc4(acc, h1, l1);
            acc4(acc, h2, l2); acc4(acc, h3, l3);
            if (layer0 && lane == 0)
                accC += g_cardf[s0] + g_cardf[s1] + g_cardf[s2] + g_cardf[s3];
        }
        for (; i < dg; ++i) {
            int s = g_csrc[st + i];
            uint2 h = *(const uint2*)(sh_ + (size_t)s * HD + lane * 4);
            uint2 l = *(const uint2*)(sl_ + (size_t)s * HD + lane * 4);
            acc4(acc, h, l);
            if (layer0 && lane == 0) accC += g_cardf[s];
        }
        float di = (dg > 0) ? 1.f / (float)dg : 0.f;
        acc.x *= di; acc.y *= di; acc.z *= di; acc.w *= di;
        uint2 hv, lv;
        split2(acc.x, acc.y, hv.x, lv.x);
        split2(acc.z, acc.w, hv.y, lv.y);
        *(uint2*)(g_bsh + (size_t)n * HD + lane * 4) = hv;
        *(uint2*)(g_bsl + (size_t)n * HD + lane * 4) = lv;
        if (layer0 && lane == 0) g_meanC[n] = accC * di;
    }
}

// ---------------- HMMA fused layer (TILE 128m x 64n), 2-pass fp16 split ----------------
// D = Ah*Bh + Al*Bh = A * Bh  (full A precision; error = fp16 weight rounding)
__global__ __launch_bounds__(256, 2) void k_mma(
    const __half* __restrict__ A0h, const __half* __restrict__ A0l,
    const __half* __restrict__ A1h, const __half* __restrict__ A1l,
    int w0, int w1,
    const float* __restrict__ b0, const float* __restrict__ b1,
    const float* __restrict__ r1wl, const float* __restrict__ r1wr,
    int numOps, int do_relu,
    float* __restrict__ fout, int ostride, int ocols,
    __half* __restrict__ bh_out, __half* __restrict__ bl_out)
{
    extern __shared__ __align__(16) char smem[];
    uint32_t sb = smem_u32(smem);
    float* auxb = (float*)(smem + S_AUX);
    float* auxl = auxb + 64;
    float* auxr = auxl + 64;

    int tid = threadIdx.x;
    int wid = tid >> 5;
    int lane = tid & 31;
    int wr0 = wid * 16;
    int n0 = blockIdx.x * TILE_M;
    int c_base = blockIdx.y * 64;

    if (tid < 64) {
        int cg = c_base + tid;
        float bs = (cg < ocols) ? b0[cg] : 0.f;
        if (b1 && cg < ocols) bs += b1[cg];
        auxb[tid] = bs;
        auxl[tid] = r1wl ? r1wl[(size_t)cg * K1] : 0.f;
        auxr[tid] = r1wr ? r1wr[(size_t)cg * K1] : 0.f;
    }

    float acc[8][4];
#pragma unroll
    for (int i = 0; i < 8; i++)
#pragma unroll
        for (int j = 0; j < 4; j++) acc[i][j] = 0.f;

    int q = lane >> 3, r8 = lane & 7;
    uint32_t qrow = (uint32_t)((q & 1) * 8 + r8);
    uint32_t qkb = (uint32_t)((q >> 1) * 16);
    uint32_t a_off = (wr0 + qrow) * RS + qkb;

    for (int op = 0; op < numOps; ++op) {
        if (op) __syncthreads();
        const __half* Ah = op ? A1h : A0h;
        const __half* Al = op ? A1l : A0l;
        const __half* Wh = g_Whi[op ? w1 : w0];

        // stage A hi/lo (16B cp.async)
        {
            int r = tid >> 1, half = tid & 1;
            int m = n0 + r;
            uint32_t dh = sb + S_AHI + r * RS + half * 128;
            uint32_t dl = sb + S_ALO + r * RS + half * 128;
            if (m < Nn) {
                const char* srch = (const char*)(Ah + (size_t)m * HD + half * 64);
                const char* srcl = (const char*)(Al + (size_t)m * HD + half * 64);
#pragma unroll
                for (int qq = 0; qq < 8; ++qq) {
                    CPA(dh + qq * 16, srch + qq * 16);
                    CPA(dl + qq * 16, srcl + qq * 16);
                }
            } else {
                uint4 z = make_uint4(0, 0, 0, 0);
#pragma unroll
                for (int qq = 0; qq < 8; ++qq) {
                    *(uint4*)(smem + S_AHI + r * RS + half * 128 + qq * 16) = z;
                    *(uint4*)(smem + S_ALO + r * RS + half * 128 + qq * 16) = z;
                }
            }
        }
        // stage W hi only (64 rows of this col-half)
        {
            int r = tid >> 2, qtr = tid & 3;
            int nrow = c_base + r;
            const char* srch = (const char*)(Wh + (size_t)nrow * HD + qtr * 32);
            uint32_t dh = sb + S_WHI + r * RS + qtr * 64;
#pragma unroll
            for (int qq = 0; qq < 4; ++qq)
                CPA(dh + qq * 16, srch + qq * 16);
        }
        CPA_COMMIT();
        CPA_WAIT();
        __syncthreads();

#pragma unroll
        for (int ks = 0; ks < 8; ++ks) {
            uint32_t kb = ks * 32;
            u32 ah[4], al[4];
            LDM4(ah, sb + S_AHI + a_off + kb);
            LDM4(al, sb + S_ALO + a_off + kb);
#pragma unroll
            for (int p = 0; p < 4; ++p) {
                uint32_t boff = (p * 16 + qrow) * RS + qkb + kb;
                u32 bh[4];
                LDM4(bh, sb + S_WHI + boff);
                MMA(acc[2 * p],     ah, bh[0], bh[2]);
                MMA(acc[2 * p],     al, bh[0], bh[2]);
                MMA(acc[2 * p + 1], ah, bh[1], bh[3]);
                MMA(acc[2 * p + 1], al, bh[1], bh[3]);
            }
        }
    }

    // epilogue
    int l4 = lane >> 2, c2 = (lane & 3) * 2;
    int rA = n0 + wr0 + l4;
    int rB = rA + 8;
    float mcA = 0.f, scA = 0.f, mcB = 0.f, scB = 0.f;
    if (r1wl) {
        if (rA < Nn) { mcA = g_meanC[rA]; scA = g_cardf[rA]; }
        if (rB < Nn) { mcB = g_meanC[rB]; scB = g_cardf[rB]; }
    }
#pragma unroll
    for (int nt = 0; nt < 8; ++nt) {
        int c = nt * 8 + c2;
        int gc = c_base + c;
        float f0 = acc[nt][0] + auxb[c]     + mcA * auxl[c]     + scA * auxr[c];
        float f1 = acc[nt][1] + auxb[c + 1] + mcA * auxl[c + 1] + scA * auxr[c + 1];
        float f2 = acc[nt][2] + auxb[c]     + mcB * auxl[c]     + scB * auxr[c];
        float f3 = acc[nt][3] + auxb[c + 1] + mcB * auxl[c + 1] + scB * auxr[c + 1];
        if (do_relu) {
            f0 = fmaxf(f0, 0.f); f1 = fmaxf(f1, 0.f);
            f2 = fmaxf(f2, 0.f); f3 = fmaxf(f3, 0.f);
        }
        if (fout) {
            if (rA < Nn) {
                if (gc < ocols)     fout[(size_t)rA * ostride + gc]     = f0;
                if (gc + 1 < ocols) fout[(size_t)rA * ostride + gc + 1] = f1;
            }
            if (rB < Nn) {
                if (gc < ocols)     fout[(size_t)rB * ostride + gc]     = f2;
                if (gc + 1 < ocols) fout[(size_t)rB * ostride + gc + 1] = f3;
            }
        }
        if (bh_out) {
            u32 hw, lw;
            if (rA < Nn) {
                split2(f0, f1, hw, lw);
                *(u32*)(bh_out + (size_t)rA * HD + gc) = hw;
                *(u32*)(bl_out + (size_t)rA * HD + gc) = lw;
            }
            if (rB < Nn) {
                split2(f2, f3, hw, lw);
                *(u32*)(bh_out + (size_t)rB * HD + gc) = hw;
                *(u32*)(bl_out + (size_t)rB * HD + gc) = lw;
            }
        }
    }
}

// ---------------- launch ----------------
extern "C" void kernel_launch(void* const* d_in, const int* in_sizes, int n_in,
                              void* d_out, int out_size) {
    int ix = 0, iWl1 = 1, ibl1 = 2, iWr1 = 3, ibr1 = 4, iWl2 = 5, ibl2 = 6,
        iWr2 = 7, ibr2 = 8, iWo = 9, ibo = 10, iei = 11, icards = 12;
    if (n_in == 13) {
        int w1a[2] = {-1, -1}; int n_w1 = 0;
        int w2a[2] = {-1, -1}; int n_w2 = 0;
        int ba[4] = {-1, -1, -1, -1}; int n_b = 0;
        int f_x = -1, f_Wo = -1, f_bo = -1, f_ei = -1, f_cards = -1;
        for (int i = 0; i < n_in; i++) {
            switch (in_sizes[i]) {
                case (int)((size_t)Nn * FIN): f_x = i; break;
                case HD * K1: if (n_w1 < 2) w1a[n_w1++] = i; break;
                case HD * HD: if (n_w2 < 2) w2a[n_w2++] = i; break;
                case HD:      if (n_b < 4)  ba[n_b++]  = i; break;
                case NCARDS * HD: f_Wo = i; break;
                case NCARDS:      f_bo = i; break;
                case 2 * Ee:      f_ei = i; break;
                case Nn:          f_cards = i; break;
                default: break;
            }
        }
        if (f_x >= 0 && n_w1 == 2 && n_w2 == 2 && n_b == 4 && f_Wo >= 0 &&
            f_bo >= 0 && f_ei >= 0 && f_cards >= 0) {
            ix = f_x; iWl1 = w1a[0]; iWr1 = w1a[1]; iWl2 = w2a[0]; iWr2 = w2a[1];
            ibl1 = ba[0]; ibr1 = ba[1]; ibl2 = ba[2]; ibr2 = ba[3];
            iWo = f_Wo; ibo = f_bo; iei = f_ei; icards = f_cards;
        }
    }

    const float* x   = (const float*)d_in[ix];
    const float* Wl1 = (const float*)d_in[iWl1];
    const float* bl1 = (const float*)d_in[ibl1];
    const float* Wr1 = (const float*)d_in[iWr1];
    const float* br1 = (const float*)d_in[ibr1];
    const float* Wl2 = (const float*)d_in[iWl2];
    const float* bl2 = (const float*)d_in[ibl2];
    const float* Wr2 = (const float*)d_in[iWr2];
    const float* br2 = (const float*)d_in[ibr2];
    const float* Wo  = (const float*)d_in[iWo];
    const float* bo  = (const float*)d_in[ibo];
    const int* ei    = (const int*)d_in[iei];
    const int* cards = (const int*)d_in[icards];
    float* out = (float*)d_out;

    cudaFuncSetAttribute(k_mma, cudaFuncAttributeMaxDynamicSharedMemorySize, SMEM_DYN);

    __half *p_b0h, *p_b0l, *p_b1h, *p_b1l, *p_b2h, *p_b2l, *p_bsh, *p_bsl;
    cudaGetSymbolAddress((void**)&p_b0h, g_b0h);
    cudaGetSymbolAddress((void**)&p_b0l, g_b0l);
    cudaGetSymbolAddress((void**)&p_b1h, g_b1h);
    cudaGetSymbolAddress((void**)&p_b1l, g_b1l);
    cudaGetSymbolAddress((void**)&p_b2h, g_b2h);
    cudaGetSymbolAddress((void**)&p_b2l, g_b2l);
    cudaGetSymbolAddress((void**)&p_bsh, g_bsh);
    cudaGetSymbolAddress((void**)&p_bsl, g_bsl);

    dim3 mg(NTILES, 2);

    k_init<<<(Nn + 255) / 256, 256>>>(ei);
    k_setupC<<<NB_CONCAT + NB_DEG + NB_PREP, 256>>>(x, cards, ei, Wl1, Wr1, Wl2, Wr2, Wo);
    k_scanA<<<(Nn + 1023) / 1024, 1024>>>();
    k_place<<<(Ee + 255) / 256, 256>>>(ei);

    // layer 1
    k_gather<<<2048, 256>>>(p_b0h, p_b0l, 1);
    k_mma<<<mg, 256, SMEM_DYN>>>(p_bsh, p_bsl, p_b0h, p_b0l, 0, 1, bl1, br1,
                                 Wl1 + 128, Wr1 + 128, 2, 1,
                                 nullptr, 0, HD, p_b1h, p_b1l);

    // layer 2
    k_gather<<<2048, 256>>>(p_b1h, p_b1l, 0);
    k_mma<<<mg, 256, SMEM_DYN>>>(p_bsh, p_bsl, p_b1h, p_b1l, 2, 3, bl2, br2,
                                 nullptr, nullptr, 2, 1,
                                 nullptr, 0, HD, p_b2h, p_b2l);

    // output head
    k_mma<<<mg, 256, SMEM_DYN>>>(p_b2h, p_b2l, nullptr, nullptr, 4, 4, bo, nullptr,
                                 nullptr, nullptr, 1, 0,
                                 out, NCARDS, NCARDS, nullptr, nullptr);
}

// round 15
// speedup vs baseline: 2.0273x; 1.5545x over previous
#include <cuda_runtime.h>
#include <cuda_fp16.h>
#include <cstdint>

#define Nn 100000
#define Ee 1600000
#define FIN 128
#define K1 129
#define HD 128
#define NCARDS 110
#define TILE_M 128
#define NTILES ((Nn + TILE_M - 1) / TILE_M)   // 782

typedef unsigned int u32;

// ---------------- device scratch (plain fp16 features) ----------------
__device__ __half g_b0[(size_t)Nn * HD];
__device__ __half g_b1[(size_t)Nn * HD];
__device__ __half g_b2[(size_t)Nn * HD];
__device__ __half g_bs[(size_t)Nn * HD];   // mean-aggregated
__device__ float g_cardf[Nn];
__device__ float g_meanC[Nn];
// fp16 weights: 0=Wl1,1=Wr1,2=Wl2,3=Wr2,4=Wo (padded [128,128], row-major [n][k])
__device__ __half g_Whi[5][HD * HD];
__device__ int g_degc[Nn];
__device__ int g_offs[Nn];
__device__ int g_tick[Ee];
__device__ int g_csrc[Ee];
__device__ int g_tot;
__device__ int g_is64;

// ---------------- helpers ----------------
__device__ __forceinline__ unsigned load_ei(const int* p, size_t i, int is64) {
    if (is64) return (unsigned)((const long long*)p)[i];
    return (unsigned)p[i];
}
__device__ __forceinline__ uint32_t smem_u32(const void* p) {
    uint32_t a;
    asm("{ .reg .u64 t; cvta.to.shared.u64 t, %1; cvt.u32.u64 %0, t; }" : "=r"(a) : "l"(p));
    return a;
}
__device__ __forceinline__ u32 pkh2(float a, float b) {
    __half2 t = __floats2half2_rn(a, b);
    return *(u32*)&t;
}
// accumulate 4 floats from fp16 uint2
__device__ __forceinline__ void acc4(float4& a, uint2 h) {
    float2 h0 = __half22float2(*(__half2*)&h.x);
    float2 h1 = __half22float2(*(__half2*)&h.y);
    a.x += h0.x; a.y += h0.y; a.z += h1.x; a.w += h1.y;
}

#define LDM4(r, addr) \
    asm volatile("ldmatrix.sync.aligned.m8n8.x4.shared.b16 {%0,%1,%2,%3}, [%4];" \
                 : "=r"((r)[0]), "=r"((r)[1]), "=r"((r)[2]), "=r"((r)[3]) : "r"(addr))

#define MMA(c, a, bb0, bb1) \
    asm volatile("mma.sync.aligned.m16n8k16.row.col.f32.f16.f16.f32 " \
                 "{%0,%1,%2,%3},{%4,%5,%6,%7},{%8,%9},{%0,%1,%2,%3};" \
                 : "+f"((c)[0]), "+f"((c)[1]), "+f"((c)[2]), "+f"((c)[3]) \
                 : "r"((a)[0]), "r"((a)[1]), "r"((a)[2]), "r"((a)[3]), "r"(bb0), "r"(bb1))

#define CPA(dst, src) \
    asm volatile("cp.async.cg.shared.global [%0], [%1], 16;" :: "r"(dst), "l"(src))
#define CPA_COMMIT() asm volatile("cp.async.commit_group;" ::: "memory")
#define CPA_WAIT()   asm volatile("cp.async.wait_group 0;" ::: "memory")

// smem; row stride 272B = 17*16 -> conflict-free ldmatrix
#define RS 272
#define S_A 0
#define S_W 34816               // 128 rows * 272
#define S_AUX 52224             // + 64 rows * 272
#define SMEM_DYN (52224 + 3 * 64 * 4)

// ---------------- setup ----------------
__global__ void k_init(const int* __restrict__ ei32) {
    int i = blockIdx.x * blockDim.x + threadIdx.x;
    if (i < Nn) g_degc[i] = 0;
    if (i == 0) {
        g_tot = 0;
        int all_zero = 1;
        for (int w = 1; w < 64; w += 2)
            if (ei32[w] != 0) { all_zero = 0; break; }
        g_is64 = all_zero;
    }
}

#define NB_CONCAT 12500
#define NB_DEG 6250
#define NB_PREP 320

// merged: concat || deghist(+ticket) || prep_w
__global__ void k_setupC(const float* __restrict__ x, const int* __restrict__ cards,
                         const int* __restrict__ ei,
                         const float* __restrict__ Wl1, const float* __restrict__ Wr1,
                         const float* __restrict__ Wl2, const float* __restrict__ Wr2,
                         const float* __restrict__ Wo) {
    int bid = blockIdx.x;
    int tid = threadIdx.x;
    if (bid < NB_CONCAT) {
        int i = bid * 256 + tid;
        if (i >= Nn * 32) return;
        int n = i >> 5, c = (i & 31) * 4;
        float4 v = *(const float4*)(x + (size_t)n * FIN + c);
        uint2 hv;
        hv.x = pkh2(v.x, v.y);
        hv.y = pkh2(v.z, v.w);
        *(uint2*)(g_b0 + (size_t)n * HD + c) = hv;
        if ((i & 31) == 0) g_cardf[n] = (float)cards[n];
    } else if (bid < NB_CONCAT + NB_DEG) {
        int e = (bid - NB_CONCAT) * 256 + tid;
        if (e < Ee) {
            unsigned d = load_ei(ei, (size_t)Ee + e, g_is64);
            if (d < Nn) g_tick[e] = atomicAdd(&g_degc[d], 1);
        }
    } else {
        int i = (bid - NB_CONCAT - NB_DEG) * 256 + tid;
        if (i >= 5 * HD * HD) return;
        int op = i / (HD * HD);
        int r = i % (HD * HD);
        int n = r / HD, k = r % HD;
        float v = 0.f;
        if (op == 0) v = Wl1[n * K1 + k];
        else if (op == 1) v = Wr1[n * K1 + k];
        else if (op == 2) v = Wl2[n * HD + k];
        else if (op == 3) v = Wr2[n * HD + k];
        else if (n < NCARDS) v = Wo[n * HD + k];
        g_Whi[op][r] = __float2half_rn(v);
    }
}

__global__ void k_scanA() {
    __shared__ int sh[1024];
    __shared__ int base;
    int t = threadIdx.x;
    int n = blockIdx.x * 1024 + t;
    int v = (n < Nn) ? g_degc[n] : 0;
    sh[t] = v;
    __syncthreads();
    for (int off = 1; off < 1024; off <<= 1) {
        int add = (t >= off) ? sh[t - off] : 0;
        __syncthreads();
        sh[t] += add;
        __syncthreads();
    }
    if (t == 1023) base = atomicAdd(&g_tot, sh[1023]);
    __syncthreads();
    if (n < Nn) g_offs[n] = base + sh[t] - v;
}

// atomic-free place using precomputed tickets
__global__ void k_place(const int* __restrict__ ei) {
    int e = blockIdx.x * blockDim.x + threadIdx.x;
    if (e < Ee) {
        int is64 = g_is64;
        unsigned s = load_ei(ei, (size_t)e, is64);
        unsigned d = load_ei(ei, (size_t)Ee + e, is64);
        if (s < Nn && d < Nn) {
            int pos = g_offs[d] + g_tick[e];
            if (pos >= 0 && pos < Ee) g_csrc[pos] = (int)s;
        }
    }
}

// ---------------- gather mean-aggregation (fp16 src, fp32 accum, MLP=4) ----------------
__global__ void k_gather(const __half* __restrict__ sh_, int layer0) {
    int gw = (blockIdx.x * blockDim.x + threadIdx.x) >> 5;
    int lane = threadIdx.x & 31;
    int nw = (gridDim.x * blockDim.x) >> 5;
    for (int n = gw; n < Nn; n += nw) {
        int st = g_offs[n];
        int dg = g_degc[n];
        if (st < 0) st = 0;
        if (st + dg > Ee) dg = Ee - st;
        float4 acc = make_float4(0.f, 0.f, 0.f, 0.f);
        float accC = 0.f;
        int i = 0;
        for (; i + 4 <= dg; i += 4) {
            int s0 = g_csrc[st + i];
            int s1 = g_csrc[st + i + 1];
            int s2 = g_csrc[st + i + 2];
            int s3 = g_csrc[st + i + 3];
            uint2 h0 = *(const uint2*)(sh_ + (size_t)s0 * HD + lane * 4);
            uint2 h1 = *(const uint2*)(sh_ + (size_t)s1 * HD + lane * 4);
            uint2 h2 = *(const uint2*)(sh_ + (size_t)s2 * HD + lane * 4);
            uint2 h3 = *(const uint2*)(sh_ + (size_t)s3 * HD + lane * 4);
            acc4(acc, h0); acc4(acc, h1); acc4(acc, h2); acc4(acc, h3);
            if (layer0 && lane == 0)
                accC += g_cardf[s0] + g_cardf[s1] + g_cardf[s2] + g_cardf[s3];
        }
        for (; i < dg; ++i) {
            int s = g_csrc[st + i];
            uint2 h = *(const uint2*)(sh_ + (size_t)s * HD + lane * 4);
            acc4(acc, h);
            if (layer0 && lane == 0) accC += g_cardf[s];
        }
        float di = (dg > 0) ? 1.f / (float)dg : 0.f;
        uint2 hv;
        hv.x = pkh2(acc.x * di, acc.y * di);
        hv.y = pkh2(acc.z * di, acc.w * di);
        *(uint2*)(g_bs + (size_t)n * HD + lane * 4) = hv;
        if (layer0 && lane == 0) g_meanC[n] = accC * di;
    }
}

// ---------------- HMMA fused layer (TILE 128m x 64n), plain fp16 ----------------
__global__ __launch_bounds__(256, 3) void k_mma(
    const __half* __restrict__ A0, const __half* __restrict__ A1,
    int w0, int w1,
    const float* __restrict__ b0, const float* __restrict__ b1,
    const float* __restrict__ r1wl, const float* __restrict__ r1wr,
    int numOps, int do_relu,
    float* __restrict__ fout, int ostride, int ocols,
    __half* __restrict__ h_out)
{
    extern __shared__ __align__(16) char smem[];
    uint32_t sb = smem_u32(smem);
    float* auxb = (float*)(smem + S_AUX);
    float* auxl = auxb + 64;
    float* auxr = auxl + 64;

    int tid = threadIdx.x;
    int wid = tid >> 5;
    int lane = tid & 31;
    int wr0 = wid * 16;
    int n0 = blockIdx.x * TILE_M;
    int c_base = blockIdx.y * 64;

    if (tid < 64) {
        int cg = c_base + tid;
        float bs = (cg < ocols) ? b0[cg] : 0.f;
        if (b1 && cg < ocols) bs += b1[cg];
        auxb[tid] = bs;
        auxl[tid] = r1wl ? r1wl[(size_t)cg * K1] : 0.f;
        auxr[tid] = r1wr ? r1wr[(size_t)cg * K1] : 0.f;
    }

    float acc[8][4];
#pragma unroll
    for (int i = 0; i < 8; i++)
#pragma unroll
        for (int j = 0; j < 4; j++) acc[i][j] = 0.f;

    int q = lane >> 3, r8 = lane & 7;
    uint32_t qrow = (uint32_t)((q & 1) * 8 + r8);
    uint32_t qkb = (uint32_t)((q >> 1) * 16);
    uint32_t a_off = (wr0 + qrow) * RS + qkb;

    for (int op = 0; op < numOps; ++op) {
        if (op) __syncthreads();
        const __half* A = op ? A1 : A0;
        const __half* W = g_Whi[op ? w1 : w0];

        // stage A (16B cp.async)
        {
            int r = tid >> 1, half = tid & 1;
            int m = n0 + r;
            uint32_t dh = sb + S_A + r * RS + half * 128;
            if (m < Nn) {
                const char* srch = (const char*)(A + (size_t)m * HD + half * 64);
#pragma unroll
                for (int qq = 0; qq < 8; ++qq)
                    CPA(dh + qq * 16, srch + qq * 16);
            } else {
                uint4 z = make_uint4(0, 0, 0, 0);
#pragma unroll
                for (int qq = 0; qq < 8; ++qq)
                    *(uint4*)(smem + S_A + r * RS + half * 128 + qq * 16) = z;
            }
        }
        // stage W (64 rows of this col-half)
        {
            int r = tid >> 2, qtr = tid & 3;
            int nrow = c_base + r;
            const char* srch = (const char*)(W + (size_t)nrow * HD + qtr * 32);
            uint32_t dh = sb + S_W + r * RS + qtr * 64;
#pragma unroll
            for (int qq = 0; qq < 4; ++qq)
                CPA(dh + qq * 16, srch + qq * 16);
        }
        CPA_COMMIT();
        CPA_WAIT();
        __syncthreads();

#pragma unroll
        for (int ks = 0; ks < 8; ++ks) {
            uint32_t kb = ks * 32;
            u32 ah[4];
            LDM4(ah, sb + S_A + a_off + kb);
#pragma unroll
            for (int p = 0; p < 4; ++p) {
                uint32_t boff = (p * 16 + qrow) * RS + qkb + kb;
                u32 bh[4];
                LDM4(bh, sb + S_W + boff);
                MMA(acc[2 * p],     ah, bh[0], bh[2]);
                MMA(acc[2 * p + 1], ah, bh[1], bh[3]);
            }
        }
    }

    // epilogue
    int l4 = lane >> 2, c2 = (lane & 3) * 2;
    int rA = n0 + wr0 + l4;
    int rB = rA + 8;
    float mcA = 0.f, scA = 0.f, mcB = 0.f, scB = 0.f;
    if (r1wl) {
        if (rA < Nn) { mcA = g_meanC[rA]; scA = g_cardf[rA]; }
        if (rB < Nn) { mcB = g_meanC[rB]; scB = g_cardf[rB]; }
    }
#pragma unroll
    for (int nt = 0; nt < 8; ++nt) {
        int c = nt * 8 + c2;
        int gc = c_base + c;
        float f0 = acc[nt][0] + auxb[c]     + mcA * auxl[c]     + scA * auxr[c];
        float f1 = acc[nt][1] + auxb[c + 1] + mcA * auxl[c + 1] + scA * auxr[c + 1];
        float f2 = acc[nt][2] + auxb[c]     + mcB * auxl[c]     + scB * auxr[c];
        float f3 = acc[nt][3] + auxb[c + 1] + mcB * auxl[c + 1] + scB * auxr[c + 1];
        if (do_relu) {
            f0 = fmaxf(f0, 0.f); f1 = fmaxf(f1, 0.f);
            f2 = fmaxf(f2, 0.f); f3 = fmaxf(f3, 0.f);
        }
        if (fout) {
            if (rA < Nn) {
                if (gc < ocols)     fout[(size_t)rA * ostride + gc]     = f0;
                if (gc + 1 < ocols) fout[(size_t)rA * ostride + gc + 1] = f1;
            }
            if (rB < Nn) {
                if (gc < ocols)     fout[(size_t)rB * ostride + gc]     = f2;
                if (gc + 1 < ocols) fout[(size_t)rB * ostride + gc + 1] = f3;
            }
        }
        if (h_out) {
            if (rA < Nn) *(u32*)(h_out + (size_t)rA * HD + gc) = pkh2(f0, f1);
            if (rB < Nn) *(u32*)(h_out + (size_t)rB * HD + gc) = pkh2(f2, f3);
        }
    }
}

// ---------------- launch ----------------
extern "C" void kernel_launch(void* const* d_in, const int* in_sizes, int n_in,
                              void* d_out, int out_size) {
    int ix = 0, iWl1 = 1, ibl1 = 2, iWr1 = 3, ibr1 = 4, iWl2 = 5, ibl2 = 6,
        iWr2 = 7, ibr2 = 8, iWo = 9, ibo = 10, iei = 11, icards = 12;
    if (n_in == 13) {
        int w1a[2] = {-1, -1}; int n_w1 = 0;
        int w2a[2] = {-1, -1}; int n_w2 = 0;
        int ba[4] = {-1, -1, -1, -1}; int n_b = 0;
        int f_x = -1, f_Wo = -1, f_bo = -1, f_ei = -1, f_cards = -1;
        for (int i = 0; i < n_in; i++) {
            switch (in_sizes[i]) {
                case (int)((size_t)Nn * FIN): f_x = i; break;
                case HD * K1: if (n_w1 < 2) w1a[n_w1++] = i; break;
                case HD * HD: if (n_w2 < 2) w2a[n_w2++] = i; break;
                case HD:      if (n_b < 4)  ba[n_b++]  = i; break;
                case NCARDS * HD: f_Wo = i; break;
                case NCARDS:      f_bo = i; break;
                case 2 * Ee:      f_ei = i; break;
                case Nn:          f_cards = i; break;
                default: break;
            }
        }
        if (f_x >= 0 && n_w1 == 2 && n_w2 == 2 && n_b == 4 && f_Wo >= 0 &&
            f_bo >= 0 && f_ei >= 0 && f_cards >= 0) {
            ix = f_x; iWl1 = w1a[0]; iWr1 = w1a[1]; iWl2 = w2a[0]; iWr2 = w2a[1];
            ibl1 = ba[0]; ibr1 = ba[1]; ibl2 = ba[2]; ibr2 = ba[3];
            iWo = f_Wo; ibo = f_bo; iei = f_ei; icards = f_cards;
        }
    }

    const float* x   = (const float*)d_in[ix];
    const float* Wl1 = (const float*)d_in[iWl1];
    const float* bl1 = (const float*)d_in[ibl1];
    const float* Wr1 = (const float*)d_in[iWr1];
    const float* br1 = (const float*)d_in[ibr1];
    const float* Wl2 = (const float*)d_in[iWl2];
    const float* bl2 = (const float*)d_in[ibl2];
    const float* Wr2 = (const float*)d_in[iWr2];
    const float* br2 = (const float*)d_in[ibr2];
    const float* Wo  = (const float*)d_in[iWo];
    const float* bo  = (const float*)d_in[ibo];
    const int* ei    = (const int*)d_in[iei];
    const int* cards = (const int*)d_in[icards];
    float* out = (float*)d_out;

    cudaFuncSetAttribute(k_mma, cudaFuncAttributeMaxDynamicSharedMemorySize, SMEM_DYN);

    __half *p_b0, *p_b1, *p_b2, *p_bs;
    cudaGetSymbolAddress((void**)&p_b0, g_b0);
    cudaGetSymbolAddress((void**)&p_b1, g_b1);
    cudaGetSymbolAddress((void**)&p_b2, g_b2);
    cudaGetSymbolAddress((void**)&p_bs, g_bs);

    dim3 mg(NTILES, 2);

    k_init<<<(Nn + 255) / 256, 256>>>(ei);
    k_setupC<<<NB_CONCAT + NB_DEG + NB_PREP, 256>>>(x, cards, ei, Wl1, Wr1, Wl2, Wr2, Wo);
    k_scanA<<<(Nn + 1023) / 1024, 1024>>>();
    k_place<<<(Ee + 255) / 256, 256>>>(ei);

    // layer 1
    k_gather<<<2048, 256>>>(p_b0, 1);
    k_mma<<<mg, 256, SMEM_DYN>>>(p_bs, p_b0, 0, 1, bl1, br1,
                                 Wl1 + 128, Wr1 + 128, 2, 1,
                                 nullptr, 0, HD, p_b1);

    // layer 2
    k_gather<<<2048, 256>>>(p_b1, 0);
    k_mma<<<mg, 256, SMEM_DYN>>>(p_bs, p_b1, 2, 3, bl2, br2,
                                 nullptr, nullptr, 2, 1,
                                 nullptr, 0, HD, p_b2);

    // output head
    k_mma<<<mg, 256, SMEM_DYN>>>(p_b2, nullptr, 4, 4, bo, nullptr,
                                 nullptr, nullptr, 1, 0,
                                 out, NCARDS, NCARDS, nullptr);
}

// round 16
// speedup vs baseline: 2.0798x; 1.0259x over previous
#include <cuda_runtime.h>
#include <cuda_fp16.h>
#include <cstdint>

#define Nn 100000
#define Ee 1600000
#define FIN 128
#define K1 129
#define HD 128
#define NCARDS 110
#define TILE_M 128
#define NTILES ((Nn + TILE_M - 1) / TILE_M)   // 782

typedef unsigned int u32;

// ---------------- device scratch (plain fp16 features) ----------------
__device__ __half g_b0[(size_t)Nn * HD];
__device__ __half g_b1[(size_t)Nn * HD];
__device__ __half g_b2[(size_t)Nn * HD];
__device__ __half g_bs[(size_t)Nn * HD];   // mean-aggregated
__device__ float g_cardf[Nn];
__device__ float g_meanC[Nn];
// fp16 weights: 0=Wl1,1=Wr1,2=Wl2,3=Wr2,4=Wo (padded [128,128], row-major [n][k])
__device__ __half g_Whi[5][HD * HD];
__device__ int g_degc[Nn];
__device__ int g_offs[Nn];
__device__ int g_tick[Ee];
__device__ int g_csrc[Ee];
__device__ int g_tot;
__device__ int g_is64;

// ---------------- helpers ----------------
__device__ __forceinline__ unsigned load_ei(const int* p, size_t i, int is64) {
    if (is64) return (unsigned)((const long long*)p)[i];
    return (unsigned)p[i];
}
__device__ __forceinline__ uint32_t smem_u32(const void* p) {
    uint32_t a;
    asm("{ .reg .u64 t; cvta.to.shared.u64 t, %1; cvt.u32.u64 %0, t; }" : "=r"(a) : "l"(p));
    return a;
}
__device__ __forceinline__ u32 pkh2(float a, float b) {
    __half2 t = __floats2half2_rn(a, b);
    return *(u32*)&t;
}
__device__ __forceinline__ void acc4(float4& a, uint2 h) {
    float2 h0 = __half22float2(*(__half2*)&h.x);
    float2 h1 = __half22float2(*(__half2*)&h.y);
    a.x += h0.x; a.y += h0.y; a.z += h1.x; a.w += h1.y;
}

#define LDM4(r, addr) \
    asm volatile("ldmatrix.sync.aligned.m8n8.x4.shared.b16 {%0,%1,%2,%3}, [%4];" \
                 : "=r"((r)[0]), "=r"((r)[1]), "=r"((r)[2]), "=r"((r)[3]) : "r"(addr))

#define MMA(c, a, bb0, bb1) \
    asm volatile("mma.sync.aligned.m16n8k16.row.col.f32.f16.f16.f32 " \
                 "{%0,%1,%2,%3},{%4,%5,%6,%7},{%8,%9},{%0,%1,%2,%3};" \
                 : "+f"((c)[0]), "+f"((c)[1]), "+f"((c)[2]), "+f"((c)[3]) \
                 : "r"((a)[0]), "r"((a)[1]), "r"((a)[2]), "r"((a)[3]), "r"(bb0), "r"(bb1))

#define CPA(dst, src) \
    asm volatile("cp.async.cg.shared.global [%0], [%1], 16;" :: "r"(dst), "l"(src))
#define CPA_COMMIT() asm volatile("cp.async.commit_group;" ::: "memory")
#define CPA_WAIT()   asm volatile("cp.async.wait_group 0;" ::: "memory")

// smem; row stride 272B = 17*16 -> conflict-free ldmatrix
#define RS 272
#define S_A 0
#define S_W 34816               // 128 rows * 272
#define S_AUX 69632             // + 128 rows * 272
#define SMEM_DYN (69632 + 3 * 128 * 4)

// ---------------- setup ----------------
__global__ void k_detect(const int* __restrict__ ei32) {
    if (threadIdx.x == 0) {
        g_tot = 0;
        int all_zero = 1;
        for (int w = 1; w < 64; w += 2)
            if (ei32[w] != 0) { all_zero = 0; break; }
        g_is64 = all_zero;
    }
}

#define NB_CONCAT 12500
#define NB_DEG 6250
#define NB_PREP 320

// merged: concat || deghist(+ticket) || prep_w
__global__ void k_setupC(const float* __restrict__ x, const int* __restrict__ cards,
                         const int* __restrict__ ei,
                         const float* __restrict__ Wl1, const float* __restrict__ Wr1,
                         const float* __restrict__ Wl2, const float* __restrict__ Wr2,
                         const float* __restrict__ Wo) {
    int bid = blockIdx.x;
    int tid = threadIdx.x;
    if (bid < NB_CONCAT) {
        int i = bid * 256 + tid;
        if (i >= Nn * 32) return;
        int n = i >> 5, c = (i & 31) * 4;
        float4 v = *(const float4*)(x + (size_t)n * FIN + c);
        uint2 hv;
        hv.x = pkh2(v.x, v.y);
        hv.y = pkh2(v.z, v.w);
        *(uint2*)(g_b0 + (size_t)n * HD + c) = hv;
        if ((i & 31) == 0) g_cardf[n] = (float)cards[n];
    } else if (bid < NB_CONCAT + NB_DEG) {
        int e = (bid - NB_CONCAT) * 256 + tid;
        if (e < Ee) {
            unsigned d = load_ei(ei, (size_t)Ee + e, g_is64);
            if (d < Nn) g_tick[e] = atomicAdd(&g_degc[d], 1);
        }
    } else {
        int i = (bid - NB_CONCAT - NB_DEG) * 256 + tid;
        if (i >= 5 * HD * HD) return;
        int op = i / (HD * HD);
        int r = i % (HD * HD);
        int n = r / HD, k = r % HD;
        float v = 0.f;
        if (op == 0) v = Wl1[n * K1 + k];
        else if (op == 1) v = Wr1[n * K1 + k];
        else if (op == 2) v = Wl2[n * HD + k];
        else if (op == 3) v = Wr2[n * HD + k];
        else if (n < NCARDS) v = Wo[n * HD + k];
        g_Whi[op][r] = __float2half_rn(v);
    }
}

__global__ void k_scanA() {
    __shared__ int sh[1024];
    __shared__ int base;
    int t = threadIdx.x;
    int n = blockIdx.x * 1024 + t;
    int v = (n < Nn) ? g_degc[n] : 0;
    sh[t] = v;
    __syncthreads();
    for (int off = 1; off < 1024; off <<= 1) {
        int add = (t >= off) ? sh[t - off] : 0;
        __syncthreads();
        sh[t] += add;
        __syncthreads();
    }
    if (t == 1023) base = atomicAdd(&g_tot, sh[1023]);
    __syncthreads();
    if (n < Nn) g_offs[n] = base + sh[t] - v;
}

// atomic-free place using precomputed tickets
__global__ void k_place(const int* __restrict__ ei) {
    int e = blockIdx.x * blockDim.x + threadIdx.x;
    if (e < Ee) {
        int is64 = g_is64;
        unsigned s = load_ei(ei, (size_t)e, is64);
        unsigned d = load_ei(ei, (size_t)Ee + e, is64);
        if (s < Nn && d < Nn) {
            int pos = g_offs[d] + g_tick[e];
            if (pos >= 0 && pos < Ee) g_csrc[pos] = (int)s;
        }
    }
}

// ---------------- gather mean-aggregation (fp16 src, fp32 accum, MLP=4) ----------------
__global__ void k_gather(const __half* __restrict__ sh_, int layer0) {
    int gw = (blockIdx.x * blockDim.x + threadIdx.x) >> 5;
    int lane = threadIdx.x & 31;
    int nw = (gridDim.x * blockDim.x) >> 5;
    for (int n = gw; n < Nn; n += nw) {
        int st = g_offs[n];
        int dg = g_degc[n];
        if (st < 0) st = 0;
        if (st + dg > Ee) dg = Ee - st;
        float4 acc = make_float4(0.f, 0.f, 0.f, 0.f);
        float accC = 0.f;
        int i = 0;
        for (; i + 4 <= dg; i += 4) {
            int s0 = g_csrc[st + i];
            int s1 = g_csrc[st + i + 1];
            int s2 = g_csrc[st + i + 2];
            int s3 = g_csrc[st + i + 3];
            uint2 h0 = *(const uint2*)(sh_ + (size_t)s0 * HD + lane * 4);
            uint2 h1 = *(const uint2*)(sh_ + (size_t)s1 * HD + lane * 4);
            uint2 h2 = *(const uint2*)(sh_ + (size_t)s2 * HD + lane * 4);
            uint2 h3 = *(const uint2*)(sh_ + (size_t)s3 * HD + lane * 4);
            acc4(acc, h0); acc4(acc, h1); acc4(acc, h2); acc4(acc, h3);
            if (layer0 && lane == 0)
                accC += g_cardf[s0] + g_cardf[s1] + g_cardf[s2] + g_cardf[s3];
        }
        for (; i < dg; ++i) {
            int s = g_csrc[st + i];
            uint2 h = *(const uint2*)(sh_ + (size_t)s * HD + lane * 4);
            acc4(acc, h);
            if (layer0 && lane == 0) accC += g_cardf[s];
        }
        float di = (dg > 0) ? 1.f / (float)dg : 0.f;
        uint2 hv;
        hv.x = pkh2(acc.x * di, acc.y * di);
        hv.y = pkh2(acc.z * di, acc.w * di);
        *(uint2*)(g_bs + (size_t)n * HD + lane * 4) = hv;
        if (layer0 && lane == 0) g_meanC[n] = accC * di;
    }
}

// ---------------- HMMA fused layer (TILE 128m x 128n), plain fp16 ----------------
__global__ __launch_bounds__(256, 2) void k_mma(
    const __half* __restrict__ A0, const __half* __restrict__ A1,
    int w0, int w1,
    const float* __restrict__ b0, const float* __restrict__ b1,
    const float* __restrict__ r1wl, const float* __restrict__ r1wr,
    int numOps, int do_relu,
    float* __restrict__ fout, int ostride, int ocols,
    __half* __restrict__ h_out)
{
    extern __shared__ __align__(16) char smem[];
    uint32_t sb = smem_u32(smem);
    float* auxb = (float*)(smem + S_AUX);
    float* auxl = auxb + 128;
    float* auxr = auxl + 128;

    int tid = threadIdx.x;
    int wid = tid >> 5;
    int lane = tid & 31;
    int wr0 = wid * 16;
    int n0 = blockIdx.x * TILE_M;

    if (tid < 128) {
        int cg = tid;
        float bs = (cg < ocols) ? b0[cg] : 0.f;
        if (b1 && cg < ocols) bs += b1[cg];
        auxb[tid] = bs;
        auxl[tid] = r1wl ? r1wl[(size_t)cg * K1] : 0.f;
        auxr[tid] = r1wr ? r1wr[(size_t)cg * K1] : 0.f;
    }

    float acc[16][4];
#pragma unroll
    for (int i = 0; i < 16; i++)
#pragma unroll
        for (int j = 0; j < 4; j++) acc[i][j] = 0.f;

    int q = lane >> 3, r8 = lane & 7;
    uint32_t qrow = (uint32_t)((q & 1) * 8 + r8);
    uint32_t qkb = (uint32_t)((q >> 1) * 16);
    uint32_t a_off = (wr0 + qrow) * RS + qkb;

    for (int op = 0; op < numOps; ++op) {
        if (op) __syncthreads();
        const __half* A = op ? A1 : A0;
        const __half* W = g_Whi[op ? w1 : w0];

        // stage A (16B cp.async), 128 rows
        {
            int r = tid >> 1, half = tid & 1;
            int m = n0 + r;
            uint32_t dh = sb + S_A + r * RS + half * 128;
            if (m < Nn) {
                const char* srch = (const char*)(A + (size_t)m * HD + half * 64);
#pragma unroll
                for (int qq = 0; qq < 8; ++qq)
                    CPA(dh + qq * 16, srch + qq * 16);
            } else {
                uint4 z = make_uint4(0, 0, 0, 0);
#pragma unroll
                for (int qq = 0; qq < 8; ++qq)
                    *(uint4*)(smem + S_A + r * RS + half * 128 + qq * 16) = z;
            }
        }
        // stage W, 128 rows
        {
            int r = tid >> 1, half = tid & 1;
            const char* srch = (const char*)(W + (size_t)r * HD + half * 64);
            uint32_t dh = sb + S_W + r * RS + half * 128;
#pragma unroll
            for (int qq = 0; qq < 8; ++qq)
                CPA(dh + qq * 16, srch + qq * 16);
        }
        CPA_COMMIT();
        CPA_WAIT();
        __syncthreads();

#pragma unroll
        for (int ks = 0; ks < 8; ++ks) {
            uint32_t kb = ks * 32;
            u32 ah[4];
            LDM4(ah, sb + S_A + a_off + kb);
#pragma unroll
            for (int p = 0; p < 8; ++p) {
                uint32_t boff = (p * 16 + qrow) * RS + qkb + kb;
                u32 bh[4];
                LDM4(bh, sb + S_W + boff);
                MMA(acc[2 * p],     ah, bh[0], bh[2]);
                MMA(acc[2 * p + 1], ah, bh[1], bh[3]);
            }
        }
    }

    // epilogue
    int l4 = lane >> 2, c2 = (lane & 3) * 2;
    int rA = n0 + wr0 + l4;
    int rB = rA + 8;
    float mcA = 0.f, scA = 0.f, mcB = 0.f, scB = 0.f;
    if (r1wl) {
        if (rA < Nn) { mcA = g_meanC[rA]; scA = g_cardf[rA]; }
        if (rB < Nn) { mcB = g_meanC[rB]; scB = g_cardf[rB]; }
    }
#pragma unroll
    for (int nt = 0; nt < 16; ++nt) {
        int gc = nt * 8 + c2;
        float f0 = acc[nt][0] + auxb[gc]     + mcA * auxl[gc]     + scA * auxr[gc];
        float f1 = acc[nt][1] + auxb[gc + 1] + mcA * auxl[gc + 1] + scA * auxr[gc + 1];
        float f2 = acc[nt][2] + auxb[gc]     + mcB * auxl[gc]     + scB * auxr[gc];
        float f3 = acc[nt][3] + auxb[gc + 1] + mcB * auxl[gc + 1] + scB * auxr[gc + 1];
        if (do_relu) {
            f0 = fmaxf(f0, 0.f); f1 = fmaxf(f1, 0.f);
            f2 = fmaxf(f2, 0.f); f3 = fmaxf(f3, 0.f);
        }
        if (fout) {
            if (rA < Nn) {
                if (gc < ocols)     fout[(size_t)rA * ostride + gc]     = f0;
                if (gc + 1 < ocols) fout[(size_t)rA * ostride + gc + 1] = f1;
            }
            if (rB < Nn) {
                if (gc < ocols)     fout[(size_t)rB * ostride + gc]     = f2;
                if (gc + 1 < ocols) fout[(size_t)rB * ostride + gc + 1] = f3;
            }
        }
        if (h_out) {
            if (rA < Nn) *(u32*)(h_out + (size_t)rA * HD + gc) = pkh2(f0, f1);
            if (rB < Nn) *(u32*)(h_out + (size_t)rB * HD + gc) = pkh2(f2, f3);
        }
    }
}

// ---------------- launch ----------------
extern "C" void kernel_launch(void* const* d_in, const int* in_sizes, int n_in,
                              void* d_out, int out_size) {
    int ix = 0, iWl1 = 1, ibl1 = 2, iWr1 = 3, ibr1 = 4, iWl2 = 5, ibl2 = 6,
        iWr2 = 7, ibr2 = 8, iWo = 9, ibo = 10, iei = 11, icards = 12;
    if (n_in == 13) {
        int w1a[2] = {-1, -1}; int n_w1 = 0;
        int w2a[2] = {-1, -1}; int n_w2 = 0;
        int ba[4] = {-1, -1, -1, -1}; int n_b = 0;
        int f_x = -1, f_Wo = -1, f_bo = -1, f_ei = -1, f_cards = -1;
        for (int i = 0; i < n_in; i++) {
            switch (in_sizes[i]) {
                case (int)((size_t)Nn * FIN): f_x = i; break;
                case HD * K1: if (n_w1 < 2) w1a[n_w1++] = i; break;
                case HD * HD: if (n_w2 < 2) w2a[n_w2++] = i; break;
                case HD:      if (n_b < 4)  ba[n_b++]  = i; break;
                case NCARDS * HD: f_Wo = i; break;
                case NCARDS:      f_bo = i; break;
                case 2 * Ee:      f_ei = i; break;
                case Nn:          f_cards = i; break;
                default: break;
            }
        }
        if (f_x >= 0 && n_w1 == 2 && n_w2 == 2 && n_b == 4 && f_Wo >= 0 &&
            f_bo >= 0 && f_ei >= 0 && f_cards >= 0) {
            ix = f_x; iWl1 = w1a[0]; iWr1 = w1a[1]; iWl2 = w2a[0]; iWr2 = w2a[1];
            ibl1 = ba[0]; ibr1 = ba[1]; ibl2 = ba[2]; ibr2 = ba[3];
            iWo = f_Wo; ibo = f_bo; iei = f_ei; icards = f_cards;
        }
    }

    const float* x   = (const float*)d_in[ix];
    const float* Wl1 = (const float*)d_in[iWl1];
    const float* bl1 = (const float*)d_in[ibl1];
    const float* Wr1 = (const float*)d_in[iWr1];
    const float* br1 = (const float*)d_in[ibr1];
    const float* Wl2 = (const float*)d_in[iWl2];
    const float* bl2 = (const float*)d_in[ibl2];
    const float* Wr2 = (const float*)d_in[iWr2];
    const float* br2 = (const float*)d_in[ibr2];
    const float* Wo  = (const float*)d_in[iWo];
    const float* bo  = (const float*)d_in[ibo];
    const int* ei    = (const int*)d_in[iei];
    const int* cards = (const int*)d_in[icards];
    float* out = (float*)d_out;

    cudaFuncSetAttribute(k_mma, cudaFuncAttributeMaxDynamicSharedMemorySize, SMEM_DYN);

    __half *p_b0, *p_b1, *p_b2, *p_bs;
    int* p_degc;
    cudaGetSymbolAddress((void**)&p_b0, g_b0);
    cudaGetSymbolAddress((void**)&p_b1, g_b1);
    cudaGetSymbolAddress((void**)&p_b2, g_b2);
    cudaGetSymbolAddress((void**)&p_bs, g_bs);
    cudaGetSymbolAddress((void**)&p_degc, g_degc);

    cudaMemsetAsync(p_degc, 0, Nn * sizeof(int));
    k_detect<<<1, 32>>>(ei);
    k_setupC<<<NB_CONCAT + NB_DEG + NB_PREP, 256>>>(x, cards, ei, Wl1, Wr1, Wl2, Wr2, Wo);
    k_scanA<<<(Nn + 1023) / 1024, 1024>>>();
    k_place<<<(Ee + 255) / 256, 256>>>(ei);

    // layer 1
    k_gather<<<2048, 256>>>(p_b0, 1);
    k_mma<<<NTILES, 256, SMEM_DYN>>>(p_bs, p_b0, 0, 1, bl1, br1,
                                     Wl1 + 128, Wr1 + 128, 2, 1,
                                     nullptr, 0, HD, p_b1);

    // layer 2
    k_gather<<<2048, 256>>>(p_b1, 0);
    k_mma<<<NTILES, 256, SMEM_DYN>>>(p_bs, p_b1, 2, 3, bl2, br2,
                                     nullptr, nullptr, 2, 1,
                                     nullptr, 0, HD, p_b2);

    // output head
    k_mma<<<NTILES, 256, SMEM_DYN>>>(p_b2, nullptr, 4, 4, bo, nullptr,
                                     nullptr, nullptr, 1, 0,
                                     out, NCARDS, NCARDS, nullptr);
}

// round 17
// speedup vs baseline: 2.2155x; 1.0652x over previous
#include <cuda_runtime.h>
#include <cuda_fp16.h>
#include <cstdint>

#define Nn 100000
#define Ee 1600000
#define FIN 128
#define K1 129
#define HD 128
#define NCARDS 110
#define TILE_M 128
#define NTILES ((Nn + TILE_M - 1) / TILE_M)   // 782

typedef unsigned int u32;

// ---------------- device scratch (plain fp16 features) ----------------
__device__ __half g_b0[(size_t)Nn * HD];
__device__ __half g_b1[(size_t)Nn * HD];
__device__ __half g_bs[(size_t)Nn * HD];   // mean-aggregated
__device__ float g_cardf[Nn];
__device__ float g_meanC[Nn];
// fp16 weights: 0=Wl1,1=Wr1,2=Wl2,3=Wr2,4=Wo (padded [128,128], row-major [n][k])
__device__ __half g_Whi[5][HD * HD];
__device__ int g_degc[Nn];
__device__ int g_offs[Nn];
__device__ int g_tick[Ee];
__device__ int g_csrc[Ee];
__device__ int g_tot;
__device__ int g_is64;

// ---------------- helpers ----------------
__device__ __forceinline__ unsigned load_ei(const int* p, size_t i, int is64) {
    if (is64) return (unsigned)((const long long*)p)[i];
    return (unsigned)p[i];
}
__device__ __forceinline__ uint32_t smem_u32(const void* p) {
    uint32_t a;
    asm("{ .reg .u64 t; cvta.to.shared.u64 t, %1; cvt.u32.u64 %0, t; }" : "=r"(a) : "l"(p));
    return a;
}
__device__ __forceinline__ u32 pkh2(float a, float b) {
    __half2 t = __floats2half2_rn(a, b);
    return *(u32*)&t;
}
__device__ __forceinline__ void acc4(float4& a, uint2 h) {
    float2 h0 = __half22float2(*(__half2*)&h.x);
    float2 h1 = __half22float2(*(__half2*)&h.y);
    a.x += h0.x; a.y += h0.y; a.z += h1.x; a.w += h1.y;
}

#define LDM4(r, addr) \
    asm volatile("ldmatrix.sync.aligned.m8n8.x4.shared.b16 {%0,%1,%2,%3}, [%4];" \
                 : "=r"((r)[0]), "=r"((r)[1]), "=r"((r)[2]), "=r"((r)[3]) : "r"(addr))

#define MMA(c, a, bb0, bb1) \
    asm volatile("mma.sync.aligned.m16n8k16.row.col.f32.f16.f16.f32 " \
                 "{%0,%1,%2,%3},{%4,%5,%6,%7},{%8,%9},{%0,%1,%2,%3};" \
                 : "+f"((c)[0]), "+f"((c)[1]), "+f"((c)[2]), "+f"((c)[3]) \
                 : "r"((a)[0]), "r"((a)[1]), "r"((a)[2]), "r"((a)[3]), "r"(bb0), "r"(bb1))

#define CPA(dst, src) \
    asm volatile("cp.async.cg.shared.global [%0], [%1], 16;" :: "r"(dst), "l"(src))
#define CPA_COMMIT() asm volatile("cp.async.commit_group;" ::: "memory")
#define CPA_WAIT()   asm volatile("cp.async.wait_group 0;" ::: "memory")

// smem; row stride 272B = 17*16 -> conflict-free ldmatrix
#define RS 272
#define S_A 0
#define S_W 34816               // 128 rows * 272
#define S_AUX 69632             // + 128 rows * 272
#define SMEM_DYN (69632 + 3 * 128 * 4)

// ---------------- setup ----------------
__global__ void k_detect(const int* __restrict__ ei32) {
    if (threadIdx.x == 0) {
        g_tot = 0;
        int all_zero = 1;
        for (int w = 1; w < 64; w += 2)
            if (ei32[w] != 0) { all_zero = 0; break; }
        g_is64 = all_zero;
    }
}

#define NB_CONCAT 12500
#define NB_DEG 6250
#define NB_PREP 320

// merged: concat || deghist(+ticket) || prep_w
__global__ void k_setupC(const float* __restrict__ x, const int* __restrict__ cards,
                         const int* __restrict__ ei,
                         const float* __restrict__ Wl1, const float* __restrict__ Wr1,
                         const float* __restrict__ Wl2, const float* __restrict__ Wr2,
                         const float* __restrict__ Wo) {
    int bid = blockIdx.x;
    int tid = threadIdx.x;
    if (bid < NB_CONCAT) {
        int i = bid * 256 + tid;
        if (i >= Nn * 32) return;
        int n = i >> 5, c = (i & 31) * 4;
        float4 v = *(const float4*)(x + (size_t)n * FIN + c);
        uint2 hv;
        hv.x = pkh2(v.x, v.y);
        hv.y = pkh2(v.z, v.w);
        *(uint2*)(g_b0 + (size_t)n * HD + c) = hv;
        if ((i & 31) == 0) g_cardf[n] = (float)cards[n];
    } else if (bid < NB_CONCAT + NB_DEG) {
        int e = (bid - NB_CONCAT) * 256 + tid;
        if (e < Ee) {
            unsigned d = load_ei(ei, (size_t)Ee + e, g_is64);
            if (d < Nn) g_tick[e] = atomicAdd(&g_degc[d], 1);
        }
    } else {
        int i = (bid - NB_CONCAT - NB_DEG) * 256 + tid;
        if (i >= 5 * HD * HD) return;
        int op = i / (HD * HD);
        int r = i % (HD * HD);
        int n = r / HD, k = r % HD;
        float v = 0.f;
        if (op == 0) v = Wl1[n * K1 + k];
        else if (op == 1) v = Wr1[n * K1 + k];
        else if (op == 2) v = Wl2[n * HD + k];
        else if (op == 3) v = Wr2[n * HD + k];
        else if (n < NCARDS) v = Wo[n * HD + k];
        g_Whi[op][r] = __float2half_rn(v);
    }
}

__global__ void k_scanA() {
    __shared__ int sh[1024];
    __shared__ int base;
    int t = threadIdx.x;
    int n = blockIdx.x * 1024 + t;
    int v = (n < Nn) ? g_degc[n] : 0;
    sh[t] = v;
    __syncthreads();
    for (int off = 1; off < 1024; off <<= 1) {
        int add = (t >= off) ? sh[t - off] : 0;
        __syncthreads();
        sh[t] += add;
        __syncthreads();
    }
    if (t == 1023) base = atomicAdd(&g_tot, sh[1023]);
    __syncthreads();
    if (n < Nn) g_offs[n] = base + sh[t] - v;
}

// atomic-free place using precomputed tickets
__global__ void k_place(const int* __restrict__ ei) {
    int e = blockIdx.x * blockDim.x + threadIdx.x;
    if (e < Ee) {
        int is64 = g_is64;
        unsigned s = load_ei(ei, (size_t)e, is64);
        unsigned d = load_ei(ei, (size_t)Ee + e, is64);
        if (s < Nn && d < Nn) {
            int pos = g_offs[d] + g_tick[e];
            if (pos >= 0 && pos < Ee) g_csrc[pos] = (int)s;
        }
    }
}

// ---------------- gather mean-aggregation (fp16 src, fp32 accum, MLP=4) ----------------
__global__ void k_gather(const __half* __restrict__ sh_, int layer0) {
    int gw = (blockIdx.x * blockDim.x + threadIdx.x) >> 5;
    int lane = threadIdx.x & 31;
    int nw = (gridDim.x * blockDim.x) >> 5;
    for (int n = gw; n < Nn; n += nw) {
        int st = g_offs[n];
        int dg = g_degc[n];
        if (st < 0) st = 0;
        if (st + dg > Ee) dg = Ee - st;
        float4 acc = make_float4(0.f, 0.f, 0.f, 0.f);
        float accC = 0.f;
        int i = 0;
        for (; i + 4 <= dg; i += 4) {
            int s0 = g_csrc[st + i];
            int s1 = g_csrc[st + i + 1];
            int s2 = g_csrc[st + i + 2];
            int s3 = g_csrc[st + i + 3];
            uint2 h0 = *(const uint2*)(sh_ + (size_t)s0 * HD + lane * 4);
            uint2 h1 = *(const uint2*)(sh_ + (size_t)s1 * HD + lane * 4);
            uint2 h2 = *(const uint2*)(sh_ + (size_t)s2 * HD + lane * 4);
            uint2 h3 = *(const uint2*)(sh_ + (size_t)s3 * HD + lane * 4);
            acc4(acc, h0); acc4(acc, h1); acc4(acc, h2); acc4(acc, h3);
            if (layer0 && lane == 0)
                accC += g_cardf[s0] + g_cardf[s1] + g_cardf[s2] + g_cardf[s3];
        }
        for (; i < dg; ++i) {
            int s = g_csrc[st + i];
            uint2 h = *(const uint2*)(sh_ + (size_t)s * HD + lane * 4);
            acc4(acc, h);
            if (layer0 && lane == 0) accC += g_cardf[s];
        }
        float di = (dg > 0) ? 1.f / (float)dg : 0.f;
        uint2 hv;
        hv.x = pkh2(acc.x * di, acc.y * di);
        hv.y = pkh2(acc.z * di, acc.w * di);
        *(uint2*)(g_bs + (size_t)n * HD + lane * 4) = hv;
        if (layer0 && lane == 0) g_meanC[n] = accC * di;
    }
}

// ---------------- HMMA fused layer (TILE 128m x 128n), optional fused output head ----------------
__global__ __launch_bounds__(256, 2) void k_mma(
    const __half* __restrict__ A0, const __half* __restrict__ A1,
    int w0, int w1,
    const float* __restrict__ b0, const float* __restrict__ b1,
    const float* __restrict__ r1wl, const float* __restrict__ r1wr,
    int numOps, int do_relu,
    __half* __restrict__ h_out,
    int wTail, const float* __restrict__ bTail,
    float* __restrict__ fout, int ostride, int ocols)
{
    extern __shared__ __align__(16) char smem[];
    uint32_t sb = smem_u32(smem);
    float* auxb = (float*)(smem + S_AUX);
    float* auxl = auxb + 128;
    float* auxr = auxl + 128;

    int tid = threadIdx.x;
    int wid = tid >> 5;
    int lane = tid & 31;
    int wr0 = wid * 16;
    int n0 = blockIdx.x * TILE_M;

    if (tid < 128) {
        int cg = tid;
        float bs = b0[cg];
        if (b1) bs += b1[cg];
        auxb[tid] = bs;
        auxl[tid] = r1wl ? r1wl[(size_t)cg * K1] : 0.f;
        auxr[tid] = r1wr ? r1wr[(size_t)cg * K1] : 0.f;
    }

    float acc[16][4];
#pragma unroll
    for (int i = 0; i < 16; i++)
#pragma unroll
        for (int j = 0; j < 4; j++) acc[i][j] = 0.f;

    int q = lane >> 3, r8 = lane & 7;
    uint32_t qrow = (uint32_t)((q & 1) * 8 + r8);
    uint32_t qkb = (uint32_t)((q >> 1) * 16);
    uint32_t a_off = (wr0 + qrow) * RS + qkb;

    for (int op = 0; op < numOps; ++op) {
        if (op) __syncthreads();
        const __half* A = op ? A1 : A0;
        const __half* W = g_Whi[op ? w1 : w0];

        // stage A (16B cp.async), 128 rows
        {
            int r = tid >> 1, half = tid & 1;
            int m = n0 + r;
            uint32_t dh = sb + S_A + r * RS + half * 128;
            if (m < Nn) {
                const char* srch = (const char*)(A + (size_t)m * HD + half * 64);
#pragma unroll
                for (int qq = 0; qq < 8; ++qq)
                    CPA(dh + qq * 16, srch + qq * 16);
            } else {
                uint4 z = make_uint4(0, 0, 0, 0);
#pragma unroll
                for (int qq = 0; qq < 8; ++qq)
                    *(uint4*)(smem + S_A + r * RS + half * 128 + qq * 16) = z;
            }
        }
        // stage W, 128 rows
        {
            int r = tid >> 1, half = tid & 1;
            const char* srch = (const char*)(W + (size_t)r * HD + half * 64);
            uint32_t dh = sb + S_W + r * RS + half * 128;
#pragma unroll
            for (int qq = 0; qq < 8; ++qq)
                CPA(dh + qq * 16, srch + qq * 16);
        }
        CPA_COMMIT();
        CPA_WAIT();
        __syncthreads();

#pragma unroll
        for (int ks = 0; ks < 8; ++ks) {
            uint32_t kb = ks * 32;
            u32 ah[4];
            LDM4(ah, sb + S_A + a_off + kb);
#pragma unroll
            for (int p = 0; p < 8; ++p) {
                uint32_t boff = (p * 16 + qrow) * RS + qkb + kb;
                u32 bh[4];
                LDM4(bh, sb + S_W + boff);
                MMA(acc[2 * p],     ah, bh[0], bh[2]);
                MMA(acc[2 * p + 1], ah, bh[1], bh[3]);
            }
        }
    }

    // ---- main epilogue ----
    int l4 = lane >> 2, c2 = (lane & 3) * 2;
    int rowA = wr0 + l4;
    int rowB = rowA + 8;
    int rA = n0 + rowA;
    int rB = n0 + rowB;
    float mcA = 0.f, scA = 0.f, mcB = 0.f, scB = 0.f;
    if (r1wl) {
        if (rA < Nn) { mcA = g_meanC[rA]; scA = g_cardf[rA]; }
        if (rB < Nn) { mcB = g_meanC[rB]; scB = g_cardf[rB]; }
    }
#pragma unroll
    for (int nt = 0; nt < 16; ++nt) {
        int gc = nt * 8 + c2;
        float f0 = acc[nt][0] + auxb[gc]     + mcA * auxl[gc]     + scA * auxr[gc];
        float f1 = acc[nt][1] + auxb[gc + 1] + mcA * auxl[gc + 1] + scA * auxr[gc + 1];
        float f2 = acc[nt][2] + auxb[gc]     + mcB * auxl[gc]     + scB * auxr[gc];
        float f3 = acc[nt][3] + auxb[gc + 1] + mcB * auxl[gc + 1] + scB * auxr[gc + 1];
        if (do_relu) {
            f0 = fmaxf(f0, 0.f); f1 = fmaxf(f1, 0.f);
            f2 = fmaxf(f2, 0.f); f3 = fmaxf(f3, 0.f);
        }
        if (wTail >= 0) {
            *(u32*)(smem + S_A + rowA * RS + gc * 2) = pkh2(f0, f1);
            *(u32*)(smem + S_A + rowB * RS + gc * 2) = pkh2(f2, f3);
        } else {
            if (rA < Nn) *(u32*)(h_out + (size_t)rA * HD + gc) = pkh2(f0, f1);
            if (rB < Nn) *(u32*)(h_out + (size_t)rB * HD + gc) = pkh2(f2, f3);
        }
    }

    if (wTail < 0) return;

    // ---- fused output head: out = h2 @ Wo^T + bo ----
    __syncthreads();
    {
        int r = tid >> 1, half = tid & 1;
        const char* srch = (const char*)(g_Whi[wTail] + (size_t)r * HD + half * 64);
        uint32_t dh = sb + S_W + r * RS + half * 128;
#pragma unroll
        for (int qq = 0; qq < 8; ++qq)
            CPA(dh + qq * 16, srch + qq * 16);
    }
    if (tid < 128) auxb[tid] = (tid < ocols) ? bTail[tid] : 0.f;
    CPA_COMMIT();
    CPA_WAIT();
    __syncthreads();

#pragma unroll
    for (int i = 0; i < 16; i++)
#pragma unroll
        for (int j = 0; j < 4; j++) acc[i][j] = 0.f;

#pragma unroll
    for (int ks = 0; ks < 8; ++ks) {
        uint32_t kb = ks * 32;
        u32 ah[4];
        LDM4(ah, sb + S_A + a_off + kb);
#pragma unroll
        for (int p = 0; p < 8; ++p) {
            uint32_t boff = (p * 16 + qrow) * RS + qkb + kb;
            u32 bh[4];
            LDM4(bh, sb + S_W + boff);
            MMA(acc[2 * p],     ah, bh[0], bh[2]);
            MMA(acc[2 * p + 1], ah, bh[1], bh[3]);
        }
    }

#pragma unroll
    for (int nt = 0; nt < 16; ++nt) {
        int gc = nt * 8 + c2;
        if (rA < Nn) {
            if (gc < ocols)     fout[(size_t)rA * ostride + gc]     = acc[nt][0] + auxb[gc];
            if (gc + 1 < ocols) fout[(size_t)rA * ostride + gc + 1] = acc[nt][1] + auxb[gc + 1];
        }
        if (rB < Nn) {
            if (gc < ocols)     fout[(size_t)rB * ostride + gc]     = acc[nt][2] + auxb[gc];
            if (gc + 1 < ocols) fout[(size_t)rB * ostride + gc + 1] = acc[nt][3] + auxb[gc + 1];
        }
    }
}

// ---------------- launch ----------------
extern "C" void kernel_launch(void* const* d_in, const int* in_sizes, int n_in,
                              void* d_out, int out_size) {
    int ix = 0, iWl1 = 1, ibl1 = 2, iWr1 = 3, ibr1 = 4, iWl2 = 5, ibl2 = 6,
        iWr2 = 7, ibr2 = 8, iWo = 9, ibo = 10, iei = 11, icards = 12;
    if (n_in == 13) {
        int w1a[2] = {-1, -1}; int n_w1 = 0;
        int w2a[2] = {-1, -1}; int n_w2 = 0;
        int ba[4] = {-1, -1, -1, -1}; int n_b = 0;
        int f_x = -1, f_Wo = -1, f_bo = -1, f_ei = -1, f_cards = -1;
        for (int i = 0; i < n_in; i++) {
            switch (in_sizes[i]) {
                case (int)((size_t)Nn * FIN): f_x = i; break;
                case HD * K1: if (n_w1 < 2) w1a[n_w1++] = i; break;
                case HD * HD: if (n_w2 < 2) w2a[n_w2++] = i; break;
                case HD:      if (n_b < 4)  ba[n_b++]  = i; break;
                case NCARDS * HD: f_Wo = i; break;
                case NCARDS:      f_bo = i; break;
                case 2 * Ee:      f_ei = i; break;
                case Nn:          f_cards = i; break;
                default: break;
            }
        }
        if (f_x >= 0 && n_w1 == 2 && n_w2 == 2 && n_b == 4 && f_Wo >= 0 &&
            f_bo >= 0 && f_ei >= 0 && f_cards >= 0) {
            ix = f_x; iWl1 = w1a[0]; iWr1 = w1a[1]; iWl2 = w2a[0]; iWr2 = w2a[1];
            ibl1 = ba[0]; ibr1 = ba[1]; ibl2 = ba[2]; ibr2 = ba[3];
            iWo = f_Wo; ibo = f_bo; iei = f_ei; icards = f_cards;
        }
    }

    const float* x   = (const float*)d_in[ix];
    const float* Wl1 = (const float*)d_in[iWl1];
    const float* bl1 = (const float*)d_in[ibl1];
    const float* Wr1 = (const float*)d_in[iWr1];
    const float* br1 = (const float*)d_in[ibr1];
    const float* Wl2 = (const float*)d_in[iWl2];
    const float* bl2 = (const float*)d_in[ibl2];
    const float* Wr2 = (const float*)d_in[iWr2];
    const float* br2 = (const float*)d_in[ibr2];
    const float* Wo  = (const float*)d_in[iWo];
    const float* bo  = (const float*)d_in[ibo];
    const int* ei    = (const int*)d_in[iei];
    const int* cards = (const int*)d_in[icards];
    float* out = (float*)d_out;

    cudaFuncSetAttribute(k_mma, cudaFuncAttributeMaxDynamicSharedMemorySize, SMEM_DYN);

    __half *p_b0, *p_b1, *p_bs;
    int* p_degc;
    cudaGetSymbolAddress((void**)&p_b0, g_b0);
    cudaGetSymbolAddress((void**)&p_b1, g_b1);
    cudaGetSymbolAddress((void**)&p_bs, g_bs);
    cudaGetSymbolAddress((void**)&p_degc, g_degc);

    cudaMemsetAsync(p_degc, 0, Nn * sizeof(int));
    k_detect<<<1, 32>>>(ei);
    k_setupC<<<NB_CONCAT + NB_DEG + NB_PREP, 256>>>(x, cards, ei, Wl1, Wr1, Wl2, Wr2, Wo);
    k_scanA<<<(Nn + 1023) / 1024, 1024>>>();
    k_place<<<(Ee + 255) / 256, 256>>>(ei);

    // layer 1
    k_gather<<<2048, 256>>>(p_b0, 1);
    k_mma<<<NTILES, 256, SMEM_DYN>>>(p_bs, p_b0, 0, 1, bl1, br1,
                                     Wl1 + 128, Wr1 + 128, 2, 1,
                                     p_b1, -1, nullptr, nullptr, 0, 0);

    // layer 2 + fused output head
    k_gather<<<2048, 256>>>(p_b1, 0);
    k_mma<<<NTILES, 256, SMEM_DYN>>>(p_bs, p_b1, 2, 3, bl2, br2,
                                     nullptr, nullptr, 2, 1,
                                     nullptr, 4, bo, out, NCARDS, NCARDS);
}